// round 1
// baseline (speedup 1.0000x reference)
#include <cuda_runtime.h>
#include <math.h>

#define Bq   4
#define Cc   96
#define Hh   128
#define Wv   128
#define HWp  16384
#define NTOT (Bq*Cc*HWp)          // 6291456
#define PI_D 3.14159265358979323846

// ---------------- device scratch (no cudaMalloc allowed) ----------------
__device__ float g_D[128*128];
__device__ float g_DT[128*128];
__device__ float g_weff1[96*96*9];
__device__ float g_weff2[96*96*9];
__device__ float g_WcombT[96*96];
__device__ float g_bcomb[96];
__device__ float g_W1T[96*384];
__device__ float g_W2T[384*96];
__device__ float g_feat[NTOT];
__device__ float g_tokA[NTOT];
__device__ float g_tokB[NTOT];
__device__ float g_cross[NTOT];
__device__ float g_dct[NTOT];
__device__ float g_energy[Bq*HWp];
__device__ float g_scale[Bq];

// ---------------- init: DCT-II orthonormal matrix (128) ----------------
__global__ void k_init_dct() {
    int t = blockIdx.x * blockDim.x + threadIdx.x;   // 16384
    int k = t >> 7, i = t & 127;
    double v = cos(PI_D * (2.0 * i + 1.0) * k / 256.0) * sqrt(2.0 / 128.0);
    if (k == 0) v *= 0.70710678118654752440;
    float f = (float)v;
    g_D[k * 128 + i]  = f;
    g_DT[i * 128 + k] = f;
}

// ---------------- LDC effective weights ----------------
__global__ void k_weff(const float* __restrict__ w, const float* __restrict__ lm,
                       const float* __restrict__ theta, int sel) {
    int t = blockIdx.x * blockDim.x + threadIdx.x;
    if (t >= 96 * 96) return;
    int co = t / 96, ci = t % 96;
    const float* ws = w + t * 9;
    float s = 0.f;
#pragma unroll
    for (int k = 0; k < 9; k++) s += ws[k];
    float scale = 1.f - theta[0] * lm[co * 96 + ci] * s;
    float* out = (sel ? g_weff2 : g_weff1) + t * 9;
#pragma unroll
    for (int k = 0; k < 9; k++) out[k] = ws[k];
    out[4] = ws[4] * scale;
}

// ---------------- combined attention weight: Wcomb = proj @ Wv ----------------
__global__ void k_wcomb(const float* __restrict__ qkv_w, const float* __restrict__ qkv_b,
                        const float* __restrict__ proj_w, const float* __restrict__ proj_b) {
    int t = blockIdx.x * blockDim.x + threadIdx.x;
    if (t < 96 * 96) {
        int k = t / 96, i = t % 96;
        float s = 0.f;
        for (int m = 0; m < 96; m++)
            s += proj_w[i * 96 + m] * qkv_w[(192 + m) * 96 + k];
        g_WcombT[k * 96 + i] = s;
    }
    if (t < 96) {
        float s = proj_b[t];
        for (int m = 0; m < 96; m++)
            s += proj_w[t * 96 + m] * qkv_b[192 + m];
        g_bcomb[t] = s;
    }
}

// ---------------- MLP weight transposes ----------------
__global__ void k_mlpT(const float* __restrict__ w1, const float* __restrict__ w2) {
    int t = blockIdx.x * blockDim.x + threadIdx.x;
    if (t >= 96 * 384) return;
    { int k = t / 384, j = t % 384; g_W1T[t] = w1[j * 96 + k]; }
    { int k = t / 96,  i = t % 96;  g_W2T[t] = w2[i * 384 + k]; }
}

// ---------------- fused double conv: feat = conv1(x1) + conv2(x2) ----------------
__global__ void __launch_bounds__(256)
k_conv(const float* __restrict__ x1, const float* __restrict__ x2) {
    __shared__ float s1[34 * 36], s2[34 * 36], wg1[72], wg2[72];
    int tid = threadIdx.x;
    int b   = blockIdx.z;
    int cob = blockIdx.y * 8;
    int bt  = blockIdx.x;
    int y0  = (bt >> 2) * 32, x0 = (bt & 3) * 32;
    const float* X1 = x1 + (size_t)b * 96 * HWp;
    const float* X2 = x2 + (size_t)b * 96 * HWp;
    int ty = tid >> 4, tx = tid & 15;
    int py = ty * 2, px = tx * 2;

    float acc[8][4];
#pragma unroll
    for (int i = 0; i < 8; i++)
#pragma unroll
        for (int j = 0; j < 4; j++) acc[i][j] = 0.f;

    for (int ci = 0; ci < 96; ci++) {
        if (tid < 144) {
            int half = tid / 72, r = tid % 72;
            int co = r / 9, k = r % 9;
            float v = half == 0 ? g_weff1[(cob + co) * 864 + ci * 9 + k]
                                : g_weff2[(cob + co) * 864 + ci * 9 + k];
            if (half == 0) wg1[r] = v; else wg2[r] = v;
        }
        const float* p1g = X1 + ci * HWp;
        const float* p2g = X2 + ci * HWp;
        for (int l = tid; l < 1156; l += 256) {
            int r = l / 34, c = l % 34;
            int gy = y0 - 1 + r, gx = x0 - 1 + c;
            bool ok = (gy >= 0 && gy < 128 && gx >= 0 && gx < 128);
            s1[r * 36 + c] = ok ? p1g[gy * 128 + gx] : 0.f;
            s2[r * 36 + c] = ok ? p2g[gy * 128 + gx] : 0.f;
        }
        __syncthreads();

        float a1[4][4], a2[4][4];
#pragma unroll
        for (int i = 0; i < 4; i++)
#pragma unroll
            for (int j = 0; j < 4; j++) {
                a1[i][j] = s1[(py + i) * 36 + px + j];
                a2[i][j] = s2[(py + i) * 36 + px + j];
            }
#pragma unroll
        for (int co = 0; co < 8; co++) {
#pragma unroll
            for (int ky = 0; ky < 3; ky++)
#pragma unroll
                for (int kx = 0; kx < 3; kx++) {
                    float w1 = wg1[co * 9 + ky * 3 + kx];
                    float w2 = wg2[co * 9 + ky * 3 + kx];
                    acc[co][0] += w1 * a1[ky][kx]       + w2 * a2[ky][kx];
                    acc[co][1] += w1 * a1[ky][kx + 1]   + w2 * a2[ky][kx + 1];
                    acc[co][2] += w1 * a1[ky + 1][kx]   + w2 * a2[ky + 1][kx];
                    acc[co][3] += w1 * a1[ky + 1][kx + 1] + w2 * a2[ky + 1][kx + 1];
                }
        }
        __syncthreads();
    }
#pragma unroll
    for (int co = 0; co < 8; co++) {
        float* d = g_feat + ((size_t)(b * 96 + cob + co)) * HWp;
        d[(y0 + py) * 128 + x0 + px]         = acc[co][0];
        d[(y0 + py) * 128 + x0 + px + 1]     = acc[co][1];
        d[(y0 + py + 1) * 128 + x0 + px]     = acc[co][2];
        d[(y0 + py + 1) * 128 + x0 + px + 1] = acc[co][3];
    }
}

// ---------------- transpose CHW -> token-major, fused + 2*(x1+x2) ----------------
__global__ void k_t1(const float* __restrict__ x1, const float* __restrict__ x2) {
    __shared__ float tile[32][33];
    int b = blockIdx.z, c0 = blockIdx.y * 32, p0 = blockIdx.x * 32;
    int tx = threadIdx.x, ty0 = threadIdx.y;
    for (int yy = ty0; yy < 32; yy += 8) {
        size_t idx = (size_t)(b * 96 + c0 + yy) * HWp + p0 + tx;
        tile[yy][tx] = g_feat[idx] + 2.f * (x1[idx] + x2[idx]);
    }
    __syncthreads();
    for (int yy = ty0; yy < 32; yy += 8)
        g_tokA[(size_t)(b * HWp + p0 + yy) * 96 + c0 + tx] = tile[tx][yy];
}

// ---------------- swin attention (folded): t2 = t + LN1(t) @ WcombT + bcomb ----------------
__global__ void __launch_bounds__(256)
k_attn(const float* __restrict__ g1, const float* __restrict__ b1) {
    __shared__ float tns[8][4][96];
    int warp = threadIdx.x >> 5, lane = threadIdx.x & 31;
    int tokbase = blockIdx.x * 32 + warp * 4;
    float tv[4][3];
#pragma unroll
    for (int tt = 0; tt < 4; tt++) {
        const float* tp = g_tokA + (size_t)(tokbase + tt) * 96;
        float a = tp[lane], bb = tp[lane + 32], cc = tp[lane + 64];
        tv[tt][0] = a; tv[tt][1] = bb; tv[tt][2] = cc;
        float s = a + bb + cc;
#pragma unroll
        for (int o = 16; o; o >>= 1) s += __shfl_xor_sync(0xffffffff, s, o);
        float m = s / 96.f;
        float d0 = a - m, d1 = bb - m, d2 = cc - m;
        float q = d0 * d0 + d1 * d1 + d2 * d2;
#pragma unroll
        for (int o = 16; o; o >>= 1) q += __shfl_xor_sync(0xffffffff, q, o);
        float rstd = rsqrtf(q / 96.f + 1e-5f);
        tns[warp][tt][lane]      = d0 * rstd * g1[lane]      + b1[lane];
        tns[warp][tt][lane + 32] = d1 * rstd * g1[lane + 32] + b1[lane + 32];
        tns[warp][tt][lane + 64] = d2 * rstd * g1[lane + 64] + b1[lane + 64];
    }
    __syncwarp();
    float acc[4][3];
#pragma unroll
    for (int tt = 0; tt < 4; tt++) acc[tt][0] = acc[tt][1] = acc[tt][2] = 0.f;
    for (int k = 0; k < 96; k++) {
        float w0 = g_WcombT[k * 96 + lane];
        float w1 = g_WcombT[k * 96 + lane + 32];
        float w2 = g_WcombT[k * 96 + lane + 64];
#pragma unroll
        for (int tt = 0; tt < 4; tt++) {
            float s = tns[warp][tt][k];
            acc[tt][0] += s * w0; acc[tt][1] += s * w1; acc[tt][2] += s * w2;
        }
    }
#pragma unroll
    for (int tt = 0; tt < 4; tt++) {
        float* op = g_tokB + (size_t)(tokbase + tt) * 96;
        op[lane]      = tv[tt][0] + acc[tt][0] + g_bcomb[lane];
        op[lane + 32] = tv[tt][1] + acc[tt][1] + g_bcomb[lane + 32];
        op[lane + 64] = tv[tt][2] + acc[tt][2] + g_bcomb[lane + 64];
    }
}

// ---------------- swin MLP: t3 = t2 + GELU(LN2(t2)@W1T+b1)@W2T+b2 ----------------
__global__ void __launch_bounds__(256)
k_mlp(const float* __restrict__ g2, const float* __restrict__ b2,
      const float* __restrict__ mb1, const float* __restrict__ mb2) {
    __shared__ float tn2[8][2][96];
    __shared__ float hs[8][2][384];
    int warp = threadIdx.x >> 5, lane = threadIdx.x & 31;
    int tokbase = blockIdx.x * 16 + warp * 2;
    float tv[2][3];
#pragma unroll
    for (int tt = 0; tt < 2; tt++) {
        const float* tp = g_tokB + (size_t)(tokbase + tt) * 96;
        float a = tp[lane], bb = tp[lane + 32], cc = tp[lane + 64];
        tv[tt][0] = a; tv[tt][1] = bb; tv[tt][2] = cc;
        float s = a + bb + cc;
#pragma unroll
        for (int o = 16; o; o >>= 1) s += __shfl_xor_sync(0xffffffff, s, o);
        float m = s / 96.f;
        float d0 = a - m, d1 = bb - m, d2 = cc - m;
        float q = d0 * d0 + d1 * d1 + d2 * d2;
#pragma unroll
        for (int o = 16; o; o >>= 1) q += __shfl_xor_sync(0xffffffff, q, o);
        float rstd = rsqrtf(q / 96.f + 1e-5f);
        tn2[warp][tt][lane]      = d0 * rstd * g2[lane]      + b2[lane];
        tn2[warp][tt][lane + 32] = d1 * rstd * g2[lane + 32] + b2[lane + 32];
        tn2[warp][tt][lane + 64] = d2 * rstd * g2[lane + 64] + b2[lane + 64];
    }
    __syncwarp();
    float ha[2][12];
#pragma unroll
    for (int tt = 0; tt < 2; tt++)
#pragma unroll
        for (int r = 0; r < 12; r++) ha[tt][r] = 0.f;
    for (int k = 0; k < 96; k++) {
        const float* wr = g_W1T + k * 384;
        float w[12];
#pragma unroll
        for (int r = 0; r < 12; r++) w[r] = wr[lane + 32 * r];
#pragma unroll
        for (int tt = 0; tt < 2; tt++) {
            float s = tn2[warp][tt][k];
#pragma unroll
            for (int r = 0; r < 12; r++) ha[tt][r] += s * w[r];
        }
    }
#pragma unroll
    for (int tt = 0; tt < 2; tt++)
#pragma unroll
        for (int r = 0; r < 12; r++) {
            int j = lane + 32 * r;
            float x = ha[tt][r] + mb1[j];
            hs[warp][tt][j] = 0.5f * x * (1.f + erff(x * 0.70710678118654752f));
        }
    __syncwarp();
    float oa[2][3];
#pragma unroll
    for (int tt = 0; tt < 2; tt++) oa[tt][0] = oa[tt][1] = oa[tt][2] = 0.f;
    for (int k = 0; k < 384; k++) {
        float w0 = g_W2T[k * 96 + lane];
        float w1 = g_W2T[k * 96 + lane + 32];
        float w2 = g_W2T[k * 96 + lane + 64];
#pragma unroll
        for (int tt = 0; tt < 2; tt++) {
            float s = hs[warp][tt][k];
            oa[tt][0] += s * w0; oa[tt][1] += s * w1; oa[tt][2] += s * w2;
        }
    }
#pragma unroll
    for (int tt = 0; tt < 2; tt++) {
        float* op = g_tokA + (size_t)(tokbase + tt) * 96;
        op[lane]      = tv[tt][0] + oa[tt][0] + mb2[lane];
        op[lane + 32] = tv[tt][1] + oa[tt][1] + mb2[lane + 32];
        op[lane + 64] = tv[tt][2] + oa[tt][2] + mb2[lane + 64];
    }
}

// ---------------- transpose token-major -> CHW ----------------
__global__ void k_t2() {
    __shared__ float tile[32][33];
    int b = blockIdx.z, c0 = blockIdx.y * 32, p0 = blockIdx.x * 32;
    int tx = threadIdx.x, ty0 = threadIdx.y;
    for (int yy = ty0; yy < 32; yy += 8)
        tile[yy][tx] = g_tokA[(size_t)(b * HWp + p0 + yy) * 96 + c0 + tx];
    __syncthreads();
    for (int yy = ty0; yy < 32; yy += 8)
        g_cross[(size_t)(b * 96 + c0 + yy) * HWp + p0 + tx] = tile[tx][yy];
}

// ---------------- 2D DCT per (b,c): Z = D @ X @ D^T ----------------
__global__ void __launch_bounds__(256) k_dct() {
    extern __shared__ float sm[];
    float* Xs = sm;             // 16384
    float* Ys = sm + 16384;     // 16384
    int bc = blockIdx.x;
    int tid = threadIdx.x;
    const float* src = g_cross + (size_t)bc * HWp;
    for (int l = tid; l < 16384; l += 256) Xs[l] = src[l];
    __syncthreads();
    int j = tid & 127, rg = tid >> 7;
    for (int base = 0; base < 128; base += 4) {
        int i0 = base + rg * 2, i1 = i0 + 1;
        float a0 = 0.f, a1 = 0.f;
#pragma unroll 8
        for (int k = 0; k < 128; k++) {
            float xv = Xs[k * 128 + j];
            a0 += g_D[i0 * 128 + k] * xv;
            a1 += g_D[i1 * 128 + k] * xv;
        }
        Ys[i0 * 128 + j] = a0;
        Ys[i1 * 128 + j] = a1;
    }
    __syncthreads();
    float* dst = g_dct + (size_t)bc * HWp;
    for (int base = 0; base < 128; base += 4) {
        int i0 = base + rg * 2, i1 = i0 + 1;
        float a0 = 0.f, a1 = 0.f;
#pragma unroll 8
        for (int k = 0; k < 128; k++) {
            float dt = g_DT[k * 128 + j];
            a0 += Ys[i0 * 128 + k] * dt;
            a1 += Ys[i1 * 128 + k] * dt;
        }
        dst[i0 * 128 + j] = a0;
        dst[i1 * 128 + j] = a1;
    }
}

// ---------------- channel-mean |dct| ----------------
__global__ void k_energy() {
    int g = blockIdx.x * blockDim.x + threadIdx.x;   // 65536
    int b = g >> 14, p = g & 16383;
    float s = 0.f;
    for (int c = 0; c < 96; c++)
        s += fabsf(g_dct[(size_t)(b * 96 + c) * HWp + p]);
    g_energy[g] = s * (1.f / 96.f);
}

// ---------------- top-96 (sorted) + gate FC ----------------
__global__ void __launch_bounds__(256)
k_topk(const float* __restrict__ fw1, const float* __restrict__ fb1,
       const float* __restrict__ fw2, const float* __restrict__ fb2) {
    extern __shared__ float e[];   // 16384
    __shared__ float rv[256];
    __shared__ int   ri[256];
    __shared__ float tk[96];
    __shared__ float hh[24];
    int b = blockIdx.x, tid = threadIdx.x;
    const float* src = g_energy + b * HWp;
    for (int l = tid; l < 16384; l += 256) e[l] = src[l];
    __syncthreads();
    for (int it = 0; it < 96; it++) {
        float bv = -1e30f; int bi = 0;
        for (int l = tid; l < 16384; l += 256) {
            float v = e[l];
            if (v > bv) { bv = v; bi = l; }
        }
        rv[tid] = bv; ri[tid] = bi;
        __syncthreads();
        for (int s = 128; s; s >>= 1) {
            if (tid < s && rv[tid + s] > rv[tid]) { rv[tid] = rv[tid + s]; ri[tid] = ri[tid + s]; }
            __syncthreads();
        }
        if (tid == 0) { tk[it] = rv[0]; e[ri[0]] = -1e30f; }
        __syncthreads();
    }
    if (tid < 24) {
        float s = fb1[tid];
        for (int k = 0; k < 96; k++) s += tk[k] * fw1[tid * 96 + k];
        hh[tid] = fmaxf(s, 0.f);
    }
    __syncthreads();
    if (tid == 0) {
        float a = fb2[0];
        for (int j = 0; j < 24; j++) a += hh[j] * fw2[j];
        g_scale[b] = 1.f + 1.f / (1.f + expf(-a));
    }
}

// ---------------- epilogue: out1 = x1 + cross*scale, out2 = x2 + cross*scale ----------------
__global__ void k_final(const float* __restrict__ x1, const float* __restrict__ x2,
                        float* __restrict__ out) {
    int i = blockIdx.x * blockDim.x + threadIdx.x;
    float s = g_scale[i / (96 * HWp)];
    float cv = g_cross[i] * s;
    out[i]        = x1[i] + cv;
    out[NTOT + i] = x2[i] + cv;
}

extern "C" void kernel_launch(void* const* d_in, const int* in_sizes, int n_in,
                              void* d_out, int out_size) {
    const float* x1     = (const float*)d_in[0];
    const float* x2     = (const float*)d_in[1];
    const float* w_tx1  = (const float*)d_in[2];
    const float* lm1    = (const float*)d_in[3];
    const float* theta1 = (const float*)d_in[4];
    const float* w_tx2  = (const float*)d_in[5];
    const float* lm2    = (const float*)d_in[6];
    const float* theta2 = (const float*)d_in[7];
    const float* ln1_g  = (const float*)d_in[8];
    const float* ln1_b  = (const float*)d_in[9];
    const float* qkv_w  = (const float*)d_in[10];
    const float* qkv_b  = (const float*)d_in[11];
    const float* proj_w = (const float*)d_in[12];
    const float* proj_b = (const float*)d_in[13];
    const float* ln2_g  = (const float*)d_in[14];
    const float* ln2_b  = (const float*)d_in[15];
    const float* mlp_w1 = (const float*)d_in[16];
    const float* mlp_b1 = (const float*)d_in[17];
    const float* mlp_w2 = (const float*)d_in[18];
    const float* mlp_b2 = (const float*)d_in[19];
    const float* fc_w1  = (const float*)d_in[20];
    const float* fc_b1  = (const float*)d_in[21];
    const float* fc_w2  = (const float*)d_in[22];
    const float* fc_b2  = (const float*)d_in[23];
    float* out = (float*)d_out;

    static_assert(sizeof(float) == 4, "");
    cudaFuncSetAttribute(k_dct,  cudaFuncAttributeMaxDynamicSharedMemorySize, 131072);
    cudaFuncSetAttribute(k_topk, cudaFuncAttributeMaxDynamicSharedMemorySize, 65536);

    k_init_dct<<<64, 256>>>();
    k_weff<<<36, 256>>>(w_tx1, lm1, theta1, 0);
    k_weff<<<36, 256>>>(w_tx2, lm2, theta2, 1);
    k_wcomb<<<36, 256>>>(qkv_w, qkv_b, proj_w, proj_b);
    k_mlpT<<<144, 256>>>(mlp_w1, mlp_w2);

    k_conv<<<dim3(16, 12, 4), 256>>>(x1, x2);
    k_t1<<<dim3(512, 3, 4), dim3(32, 8)>>>(x1, x2);
    k_attn<<<2048, 256>>>(ln1_g, ln1_b);
    k_mlp<<<4096, 256>>>(ln2_g, ln2_b, mlp_b1, mlp_b2);
    k_t2<<<dim3(512, 3, 4), dim3(32, 8)>>>();
    k_dct<<<384, 256, 131072>>>();
    k_energy<<<256, 256>>>();
    k_topk<<<4, 256, 65536>>>(fc_w1, fc_b1, fc_w2, fc_b2);
    k_final<<<NTOT / 256, 256>>>(x1, x2, out);
}

// round 2
// speedup vs baseline: 1.0231x; 1.0231x over previous
#include <cuda_runtime.h>
#include <math.h>

#define Bq   4
#define Cc   96
#define Hh   128
#define Wv   128
#define HWp  16384
#define NTOT (Bq*Cc*HWp)          // 6291456

typedef unsigned long long ull;

__device__ __forceinline__ ull pk2(float lo, float hi) {
    ull r; asm("mov.b64 %0,{%1,%2};" : "=l"(r) : "f"(lo), "f"(hi)); return r;
}
__device__ __forceinline__ void upk(ull v, float& lo, float& hi) {
    asm("mov.b64 {%0,%1},%2;" : "=f"(lo), "=f"(hi) : "l"(v));
}
__device__ __forceinline__ void ffma2(ull& d, ull a, ull b) {
    asm("fma.rn.f32x2 %0,%1,%2,%0;" : "+l"(d) : "l"(a), "l"(b));
}
__device__ __forceinline__ float gelu_ex(float x) {
    return 0.5f * x * (1.f + erff(x * 0.70710678118654752f));
}

// ---------------- device scratch ----------------
__device__ float g_D[128*128];
__device__ float g_DT[128*128];
__device__ float g_Dp[128*128];     // row-paired: [(row>>1)*128 + pos]*2 + (row&1)
__device__ float g_weff1[96*96*9];
__device__ float g_weff2[96*96*9];
__device__ float g_WcombT[96*96];
__device__ float g_bcomb[96];
__device__ float g_W1T[96*384];
__device__ float g_W2T[384*96];
__device__ float g_feat[NTOT];
__device__ float g_tokA[NTOT];
__device__ float g_tokB[NTOT];
__device__ float g_cross[NTOT];
__device__ float g_dct[NTOT];
__device__ float g_energy[Bq*HWp];
__device__ float g_scale[Bq];

// ---------------- init: DCT-II orthonormal matrix (128), fp32 cospi ----------------
__global__ void k_init_dct() {
    int t = blockIdx.x * blockDim.x + threadIdx.x;   // 16384
    int k = t >> 7, i = t & 127;
    float arg = (float)((2 * i + 1) * k) * (1.0f / 256.0f);  // exact
    float v = cospif(arg) * 0.125f;                          // sqrt(2/128)=1/8 exact
    if (k == 0) v *= 0.70710678118654752440f;
    g_D[k * 128 + i]  = v;
    g_DT[i * 128 + k] = v;
    g_Dp[((k >> 1) * 128 + i) * 2 + (k & 1)] = v;
}

// ---------------- LDC effective weights ----------------
__global__ void k_weff(const float* __restrict__ w, const float* __restrict__ lm,
                       const float* __restrict__ theta, int sel) {
    int t = blockIdx.x * blockDim.x + threadIdx.x;
    if (t >= 96 * 96) return;
    int co = t / 96, ci = t % 96;
    const float* ws = w + t * 9;
    float s = 0.f;
#pragma unroll
    for (int k = 0; k < 9; k++) s += ws[k];
    float scale = 1.f - theta[0] * lm[co * 96 + ci] * s;
    float* out = (sel ? g_weff2 : g_weff1) + t * 9;
#pragma unroll
    for (int k = 0; k < 9; k++) out[k] = ws[k];
    out[4] = ws[4] * scale;
}

// ---------------- Wcomb = proj @ Wv (coalesced) ----------------
__global__ void k_wcomb(const float* __restrict__ qkv_w, const float* __restrict__ qkv_b,
                        const float* __restrict__ proj_w, const float* __restrict__ proj_b) {
    int i = blockIdx.x;
    int t = threadIdx.x;
    if (i < 96) {
        // thread t = k, coalesced over qkv_w columns
        float s = 0.f;
        for (int m = 0; m < 96; m++)
            s += proj_w[i * 96 + m] * qkv_w[(192 + m) * 96 + t];
        g_WcombT[t * 96 + i] = s;
    } else {
        float s = proj_b[t];
        for (int m = 0; m < 96; m++)
            s += proj_w[t * 96 + m] * qkv_b[192 + m];
        g_bcomb[t] = s;
    }
}

// ---------------- MLP weight transposes ----------------
__global__ void k_mlpT(const float* __restrict__ w1, const float* __restrict__ w2) {
    int t = blockIdx.x * blockDim.x + threadIdx.x;
    if (t >= 96 * 384) return;
    { int k = t / 384, j = t % 384; g_W1T[t] = w1[j * 96 + k]; }
    { int k = t / 96,  i = t % 96;  g_W2T[t] = w2[i * 384 + k]; }
}

// ---------------- fused double conv, f32x2 packed ----------------
__global__ void __launch_bounds__(256)
k_conv(const float* __restrict__ x1, const float* __restrict__ x2) {
    __shared__ __align__(16) float s1[34 * 36], s2[34 * 36];
    __shared__ ull wp1[72], wp2[72];
    int tid = threadIdx.x;
    int b   = blockIdx.z;
    int cob = blockIdx.y * 8;
    int bt  = blockIdx.x;
    int y0  = (bt >> 2) * 32, x0 = (bt & 3) * 32;
    const float* X1 = x1 + (size_t)b * 96 * HWp;
    const float* X2 = x2 + (size_t)b * 96 * HWp;
    int ty = tid >> 4, tx = tid & 15;
    int py = ty * 2, px = tx * 2;

    ull acc[8][2];
#pragma unroll
    for (int i = 0; i < 8; i++) { acc[i][0] = 0ULL; acc[i][1] = 0ULL; }

    for (int ci = 0; ci < 96; ci++) {
        if (tid < 144) {
            int half = tid / 72, r = tid % 72;
            int co = r / 9, k = r % 9;
            float v = half == 0 ? g_weff1[(cob + co) * 864 + ci * 9 + k]
                                : g_weff2[(cob + co) * 864 + ci * 9 + k];
            ull p = pk2(v, v);
            if (half == 0) wp1[r] = p; else wp2[r] = p;
        }
        const float* p1g = X1 + ci * HWp;
        const float* p2g = X2 + ci * HWp;
        for (int l = tid; l < 1156; l += 256) {
            int r = l / 34, c = l % 34;
            int gy = y0 - 1 + r, gx = x0 - 1 + c;
            bool ok = (gy >= 0 && gy < 128 && gx >= 0 && gx < 128);
            s1[r * 36 + c] = ok ? p1g[gy * 128 + gx] : 0.f;
            s2[r * 36 + c] = ok ? p2g[gy * 128 + gx] : 0.f;
        }
        __syncthreads();

        float a1v[4][4], a2v[4][4];
#pragma unroll
        for (int i = 0; i < 4; i++) {
            const float2* r1 = (const float2*)&s1[(py + i) * 36 + px];
            const float2* r2 = (const float2*)&s2[(py + i) * 36 + px];
            float2 u0 = r1[0], u1 = r1[1];
            float2 v0 = r2[0], v1 = r2[1];
            a1v[i][0] = u0.x; a1v[i][1] = u0.y; a1v[i][2] = u1.x; a1v[i][3] = u1.y;
            a2v[i][0] = v0.x; a2v[i][1] = v0.y; a2v[i][2] = v1.x; a2v[i][3] = v1.y;
        }
        ull pa1[4][3], pa2[4][3];
#pragma unroll
        for (int i = 0; i < 4; i++) {
#pragma unroll
            for (int j = 0; j < 3; j++) {
                pa1[i][j] = pk2(a1v[i][j], a1v[i][j + 1]);
                pa2[i][j] = pk2(a2v[i][j], a2v[i][j + 1]);
            }
        }
#pragma unroll
        for (int co = 0; co < 8; co++) {
            ull r0 = acc[co][0], r1 = acc[co][1];
#pragma unroll
            for (int ky = 0; ky < 3; ky++)
#pragma unroll
                for (int kx = 0; kx < 3; kx++) {
                    ull w1 = wp1[co * 9 + ky * 3 + kx];
                    ffma2(r0, pa1[ky][kx], w1);
                    ffma2(r1, pa1[ky + 1][kx], w1);
                    ull w2 = wp2[co * 9 + ky * 3 + kx];
                    ffma2(r0, pa2[ky][kx], w2);
                    ffma2(r1, pa2[ky + 1][kx], w2);
                }
            acc[co][0] = r0; acc[co][1] = r1;
        }
        __syncthreads();
    }
#pragma unroll
    for (int co = 0; co < 8; co++) {
        float* d = g_feat + ((size_t)(b * 96 + cob + co)) * HWp;
        float2 v0, v1;
        upk(acc[co][0], v0.x, v0.y);
        upk(acc[co][1], v1.x, v1.y);
        *(float2*)&d[(y0 + py) * 128 + x0 + px]     = v0;
        *(float2*)&d[(y0 + py + 1) * 128 + x0 + px] = v1;
    }
}

// ---------------- transpose CHW -> token-major, fused + 2*(x1+x2) ----------------
__global__ void k_t1(const float* __restrict__ x1, const float* __restrict__ x2) {
    __shared__ float tile[32][33];
    int b = blockIdx.z, c0 = blockIdx.y * 32, p0 = blockIdx.x * 32;
    int tx = threadIdx.x, ty0 = threadIdx.y;
    for (int yy = ty0; yy < 32; yy += 8) {
        size_t idx = (size_t)(b * 96 + c0 + yy) * HWp + p0 + tx;
        tile[yy][tx] = g_feat[idx] + 2.f * (x1[idx] + x2[idx]);
    }
    __syncthreads();
    for (int yy = ty0; yy < 32; yy += 8)
        g_tokA[(size_t)(b * HWp + p0 + yy) * 96 + c0 + tx] = tile[tx][yy];
}

// ---------------- swin attention (folded), 8 tokens/warp, f32x2 ----------------
__global__ void __launch_bounds__(256)
k_attn(const float* __restrict__ g1, const float* __restrict__ b1) {
    __shared__ float tns[8][8][96];
    int warp = threadIdx.x >> 5, lane = threadIdx.x & 31;
    int tokbase = blockIdx.x * 64 + warp * 8;
    float tv[8][3];
#pragma unroll
    for (int t = 0; t < 8; t++) {
        const float* tp = g_tokA + (size_t)(tokbase + t) * 96;
        float a = tp[lane], bb = tp[lane + 32], cc = tp[lane + 64];
        tv[t][0] = a; tv[t][1] = bb; tv[t][2] = cc;
        float s = a + bb + cc;
#pragma unroll
        for (int o = 16; o; o >>= 1) s += __shfl_xor_sync(0xffffffff, s, o);
        float m = s * (1.f / 96.f);
        float d0 = a - m, d1 = bb - m, d2 = cc - m;
        float q = d0 * d0 + d1 * d1 + d2 * d2;
#pragma unroll
        for (int o = 16; o; o >>= 1) q += __shfl_xor_sync(0xffffffff, q, o);
        float rstd = rsqrtf(q * (1.f / 96.f) + 1e-5f);
        tns[warp][t][lane]      = d0 * rstd * g1[lane]      + b1[lane];
        tns[warp][t][lane + 32] = d1 * rstd * g1[lane + 32] + b1[lane + 32];
        tns[warp][t][lane + 64] = d2 * rstd * g1[lane + 64] + b1[lane + 64];
    }
    __syncwarp();
    ull acc[4][3];
#pragma unroll
    for (int p = 0; p < 4; p++) { acc[p][0] = 0; acc[p][1] = 0; acc[p][2] = 0; }
    for (int k = 0; k < 96; k++) {
        float w0 = g_WcombT[k * 96 + lane];
        float w1 = g_WcombT[k * 96 + lane + 32];
        float w2 = g_WcombT[k * 96 + lane + 64];
        ull W0 = pk2(w0, w0), W1 = pk2(w1, w1), W2 = pk2(w2, w2);
#pragma unroll
        for (int p = 0; p < 4; p++) {
            ull sp = pk2(tns[warp][2 * p][k], tns[warp][2 * p + 1][k]);
            ffma2(acc[p][0], sp, W0);
            ffma2(acc[p][1], sp, W1);
            ffma2(acc[p][2], sp, W2);
        }
    }
#pragma unroll
    for (int p = 0; p < 4; p++) {
#pragma unroll
        for (int c = 0; c < 3; c++) {
            float o0, o1; upk(acc[p][c], o0, o1);
            int ch = lane + 32 * c;
            g_tokB[(size_t)(tokbase + 2 * p) * 96 + ch]     = tv[2 * p][c]     + o0 + g_bcomb[ch];
            g_tokB[(size_t)(tokbase + 2 * p + 1) * 96 + ch] = tv[2 * p + 1][c] + o1 + g_bcomb[ch];
        }
    }
}

// ---------------- swin MLP, 8 tokens/warp, f32x2, j-halved ----------------
__global__ void __launch_bounds__(256)
k_mlp(const float* __restrict__ g2, const float* __restrict__ b2,
      const float* __restrict__ mb1, const float* __restrict__ mb2) {
    extern __shared__ float sm[];
    float* tn2 = sm;           // [8][8][96]  = 6144 floats
    float* hs  = sm + 6144;    // [8][8][192] = 12288 floats
    int warp = threadIdx.x >> 5, lane = threadIdx.x & 31;
    int tokbase = blockIdx.x * 64 + warp * 8;
    float* tnw = tn2 + warp * 768;
    float* hsw = hs + warp * 1536;
    float tv[8][3];
#pragma unroll
    for (int t = 0; t < 8; t++) {
        const float* tp = g_tokB + (size_t)(tokbase + t) * 96;
        float a = tp[lane], bb = tp[lane + 32], cc = tp[lane + 64];
        tv[t][0] = a; tv[t][1] = bb; tv[t][2] = cc;
        float s = a + bb + cc;
#pragma unroll
        for (int o = 16; o; o >>= 1) s += __shfl_xor_sync(0xffffffff, s, o);
        float m = s * (1.f / 96.f);
        float d0 = a - m, d1 = bb - m, d2 = cc - m;
        float q = d0 * d0 + d1 * d1 + d2 * d2;
#pragma unroll
        for (int o = 16; o; o >>= 1) q += __shfl_xor_sync(0xffffffff, q, o);
        float rstd = rsqrtf(q * (1.f / 96.f) + 1e-5f);
        tnw[t * 96 + lane]      = d0 * rstd * g2[lane]      + b2[lane];
        tnw[t * 96 + lane + 32] = d1 * rstd * g2[lane + 32] + b2[lane + 32];
        tnw[t * 96 + lane + 64] = d2 * rstd * g2[lane + 64] + b2[lane + 64];
    }
    __syncwarp();
    ull oacc[4][3];
#pragma unroll
    for (int p = 0; p < 4; p++) { oacc[p][0] = 0; oacc[p][1] = 0; oacc[p][2] = 0; }

    for (int half = 0; half < 2; half++) {
        ull h[4][6];
#pragma unroll
        for (int p = 0; p < 4; p++)
#pragma unroll
            for (int r = 0; r < 6; r++) h[p][r] = 0;
        const float* w1p = g_W1T + half * 192 + lane;
        for (int k = 0; k < 96; k++) {
            ull W[6];
#pragma unroll
            for (int r = 0; r < 6; r++) {
                float wv = w1p[k * 384 + 32 * r];
                W[r] = pk2(wv, wv);
            }
#pragma unroll
            for (int p = 0; p < 4; p++) {
                ull sp = pk2(tnw[2 * p * 96 + k], tnw[(2 * p + 1) * 96 + k]);
#pragma unroll
                for (int r = 0; r < 6; r++) ffma2(h[p][r], sp, W[r]);
            }
        }
#pragma unroll
        for (int p = 0; p < 4; p++)
#pragma unroll
            for (int r = 0; r < 6; r++) {
                int j = lane + 32 * r;
                float bias = mb1[half * 192 + j];
                float x0, x1; upk(h[p][r], x0, x1);
                hsw[(2 * p) * 192 + j]     = gelu_ex(x0 + bias);
                hsw[(2 * p + 1) * 192 + j] = gelu_ex(x1 + bias);
            }
        __syncwarp();
        const float* w2p = g_W2T + (size_t)(half * 192) * 96;
        for (int j = 0; j < 192; j++) {
            float u0 = w2p[j * 96 + lane];
            float u1 = w2p[j * 96 + lane + 32];
            float u2 = w2p[j * 96 + lane + 64];
            ull U0 = pk2(u0, u0), U1 = pk2(u1, u1), U2 = pk2(u2, u2);
#pragma unroll
            for (int p = 0; p < 4; p++) {
                ull hp = pk2(hsw[2 * p * 192 + j], hsw[(2 * p + 1) * 192 + j]);
                ffma2(oacc[p][0], hp, U0);
                ffma2(oacc[p][1], hp, U1);
                ffma2(oacc[p][2], hp, U2);
            }
        }
        __syncwarp();
    }
#pragma unroll
    for (int p = 0; p < 4; p++) {
#pragma unroll
        for (int c = 0; c < 3; c++) {
            float o0, o1; upk(oacc[p][c], o0, o1);
            int ch = lane + 32 * c;
            g_tokA[(size_t)(tokbase + 2 * p) * 96 + ch]     = tv[2 * p][c]     + o0 + mb2[ch];
            g_tokA[(size_t)(tokbase + 2 * p + 1) * 96 + ch] = tv[2 * p + 1][c] + o1 + mb2[ch];
        }
    }
}

// ---------------- transpose token-major -> CHW ----------------
__global__ void k_t2() {
    __shared__ float tile[32][33];
    int b = blockIdx.z, c0 = blockIdx.y * 32, p0 = blockIdx.x * 32;
    int tx = threadIdx.x, ty0 = threadIdx.y;
    for (int yy = ty0; yy < 32; yy += 8)
        tile[yy][tx] = g_tokA[(size_t)(b * HWp + p0 + yy) * 96 + c0 + tx];
    __syncthreads();
    for (int yy = ty0; yy < 32; yy += 8)
        g_cross[(size_t)(b * 96 + c0 + yy) * HWp + p0 + tx] = tile[tx][yy];
}

// ---------------- 2D DCT per (b,c), f32x2 both stages ----------------
__global__ void __launch_bounds__(256) k_dct() {
    extern __shared__ float sm[];
    float* Xs = sm;             // 16384
    float* Ys = sm + 16384;     // 16384
    int bc = blockIdx.x;
    int tid = threadIdx.x;
    const float4* src = (const float4*)(g_cross + (size_t)bc * HWp);
    float4* Xs4 = (float4*)Xs;
    for (int l = tid; l < 4096; l += 256) Xs4[l] = src[l];
    __syncthreads();

    int jq = tid & 31;      // columns 2jq,2jq+1 and 64+2jq,65+2jq
    int ig = tid >> 5;      // 0..7
    int j0 = 2 * jq, j2 = 64 + 2 * jq;

    // Stage 1: Ys = D @ Xs
    for (int ii = 0; ii < 8; ii++) {
        int ip = ig + ii * 8;
        ull a00 = 0, a01 = 0, a10 = 0, a11 = 0;
        const float2* dp = ((const float2*)g_Dp) + ip * 128;
#pragma unroll 4
        for (int k = 0; k < 128; k++) {
            float2 d = dp[k];                       // uniform LDG.64
            ull D0 = pk2(d.x, d.x), D1 = pk2(d.y, d.y);
            ull xA = *(const ull*)&Xs[k * 128 + j0];
            ull xB = *(const ull*)&Xs[k * 128 + j2];
            ffma2(a00, xA, D0); ffma2(a01, xB, D0);
            ffma2(a10, xA, D1); ffma2(a11, xB, D1);
        }
        *(ull*)&Ys[(2 * ip) * 128 + j0]     = a00;
        *(ull*)&Ys[(2 * ip) * 128 + j2]     = a01;
        *(ull*)&Ys[(2 * ip + 1) * 128 + j0] = a10;
        *(ull*)&Ys[(2 * ip + 1) * 128 + j2] = a11;
    }
    __syncthreads();

    // Stage 2: dst = Ys @ D^T  (k-outer, acc in regs)
    ull acc[8][4];
#pragma unroll
    for (int ii = 0; ii < 8; ii++)
#pragma unroll
        for (int q = 0; q < 4; q++) acc[ii][q] = 0;
    for (int k = 0; k < 128; k++) {
        ull dtA = *(const ull*)&g_DT[k * 128 + j0];  // coalesced LDG.64
        ull dtB = *(const ull*)&g_DT[k * 128 + j2];
#pragma unroll
        for (int ii = 0; ii < 8; ii++) {
            int ip = ig + ii * 8;
            float y0 = Ys[(2 * ip) * 128 + k];       // LDS broadcast
            float y1 = Ys[(2 * ip + 1) * 128 + k];
            ull Y0 = pk2(y0, y0), Y1 = pk2(y1, y1);
            ffma2(acc[ii][0], dtA, Y0); ffma2(acc[ii][1], dtB, Y0);
            ffma2(acc[ii][2], dtA, Y1); ffma2(acc[ii][3], dtB, Y1);
        }
    }
    float* dst = g_dct + (size_t)bc * HWp;
#pragma unroll
    for (int ii = 0; ii < 8; ii++) {
        int ip = ig + ii * 8;
        *(ull*)&dst[(2 * ip) * 128 + j0]     = acc[ii][0];
        *(ull*)&dst[(2 * ip) * 128 + j2]     = acc[ii][1];
        *(ull*)&dst[(2 * ip + 1) * 128 + j0] = acc[ii][2];
        *(ull*)&dst[(2 * ip + 1) * 128 + j2] = acc[ii][3];
    }
}

// ---------------- channel-mean |dct| (float4) ----------------
__global__ void k_energy() {
    int g = blockIdx.x * blockDim.x + threadIdx.x;   // 16384
    int b = g >> 12, p4 = g & 4095;
    const float4* base = (const float4*)(g_dct + (size_t)b * 96 * HWp) + p4;
    float4 s = make_float4(0.f, 0.f, 0.f, 0.f);
    for (int c = 0; c < 96; c++) {
        float4 v = base[(size_t)c * 4096];
        s.x += fabsf(v.x); s.y += fabsf(v.y); s.z += fabsf(v.z); s.w += fabsf(v.w);
    }
    float inv = 1.f / 96.f;
    s.x *= inv; s.y *= inv; s.z *= inv; s.w *= inv;
    ((float4*)(g_energy + b * HWp))[p4] = s;
}

// ---------------- top-96 + gate FC ----------------
__global__ void __launch_bounds__(256)
k_topk(const float* __restrict__ fw1, const float* __restrict__ fb1,
       const float* __restrict__ fw2, const float* __restrict__ fb2) {
    extern __shared__ float e[];   // 16384
    __shared__ float sv[8];
    __shared__ int   si[8];
    __shared__ float tk[96];
    __shared__ float hh[24];
    int b = blockIdx.x, tid = threadIdx.x;
    int warp = tid >> 5, lane = tid & 31;
    const float4* src = (const float4*)(g_energy + b * HWp);
    float4* e4 = (float4*)e;
    for (int l = tid; l < 4096; l += 256) e4[l] = src[l];
    __syncthreads();
    for (int it = 0; it < 96; it++) {
        float bv = -1e30f; int bi = 0;
        for (int l = tid; l < 16384; l += 256) {
            float v = e[l];
            if (v > bv) { bv = v; bi = l; }
        }
#pragma unroll
        for (int o = 16; o; o >>= 1) {
            float ov = __shfl_down_sync(0xffffffff, bv, o);
            int   oi = __shfl_down_sync(0xffffffff, bi, o);
            if (ov > bv) { bv = ov; bi = oi; }
        }
        if (lane == 0) { sv[warp] = bv; si[warp] = bi; }
        __syncthreads();
        if (tid == 0) {
            float m = sv[0]; int mi = si[0];
#pragma unroll
            for (int w = 1; w < 8; w++)
                if (sv[w] > m) { m = sv[w]; mi = si[w]; }
            tk[it] = m; e[mi] = -1e30f;
        }
        __syncthreads();
    }
    if (tid < 24) {
        float s = fb1[tid];
        for (int k = 0; k < 96; k++) s += tk[k] * fw1[tid * 96 + k];
        hh[tid] = fmaxf(s, 0.f);
    }
    __syncthreads();
    if (tid == 0) {
        float a = fb2[0];
        for (int j = 0; j < 24; j++) a += hh[j] * fw2[j];
        g_scale[b] = 1.f + 1.f / (1.f + expf(-a));
    }
}

// ---------------- epilogue (float4) ----------------
__global__ void k_final(const float* __restrict__ x1, const float* __restrict__ x2,
                        float* __restrict__ out) {
    int i = blockIdx.x * blockDim.x + threadIdx.x;   // NTOT/4
    float s = g_scale[i / (96 * HWp / 4)];
    float4 c = ((const float4*)g_cross)[i];
    float4 a = ((const float4*)x1)[i];
    float4 b = ((const float4*)x2)[i];
    float4 o1, o2;
    o1.x = a.x + s * c.x; o1.y = a.y + s * c.y; o1.z = a.z + s * c.z; o1.w = a.w + s * c.w;
    o2.x = b.x + s * c.x; o2.y = b.y + s * c.y; o2.z = b.z + s * c.z; o2.w = b.w + s * c.w;
    ((float4*)out)[i]            = o1;
    ((float4*)out)[NTOT / 4 + i] = o2;
}

extern "C" void kernel_launch(void* const* d_in, const int* in_sizes, int n_in,
                              void* d_out, int out_size) {
    const float* x1     = (const float*)d_in[0];
    const float* x2     = (const float*)d_in[1];
    const float* w_tx1  = (const float*)d_in[2];
    const float* lm1    = (const float*)d_in[3];
    const float* theta1 = (const float*)d_in[4];
    const float* w_tx2  = (const float*)d_in[5];
    const float* lm2    = (const float*)d_in[6];
    const float* theta2 = (const float*)d_in[7];
    const float* ln1_g  = (const float*)d_in[8];
    const float* ln1_b  = (const float*)d_in[9];
    const float* qkv_w  = (const float*)d_in[10];
    const float* qkv_b  = (const float*)d_in[11];
    const float* proj_w = (const float*)d_in[12];
    const float* proj_b = (const float*)d_in[13];
    const float* ln2_g  = (const float*)d_in[14];
    const float* ln2_b  = (const float*)d_in[15];
    const float* mlp_w1 = (const float*)d_in[16];
    const float* mlp_b1 = (const float*)d_in[17];
    const float* mlp_w2 = (const float*)d_in[18];
    const float* mlp_b2 = (const float*)d_in[19];
    const float* fc_w1  = (const float*)d_in[20];
    const float* fc_b1  = (const float*)d_in[21];
    const float* fc_w2  = (const float*)d_in[22];
    const float* fc_b2  = (const float*)d_in[23];
    float* out = (float*)d_out;

    cudaFuncSetAttribute(k_dct,  cudaFuncAttributeMaxDynamicSharedMemorySize, 131072);
    cudaFuncSetAttribute(k_topk, cudaFuncAttributeMaxDynamicSharedMemorySize, 65536);
    cudaFuncSetAttribute(k_mlp,  cudaFuncAttributeMaxDynamicSharedMemorySize, 73728);

    k_init_dct<<<64, 256>>>();
    k_weff<<<36, 256>>>(w_tx1, lm1, theta1, 0);
    k_weff<<<36, 256>>>(w_tx2, lm2, theta2, 1);
    k_wcomb<<<97, 96>>>(qkv_w, qkv_b, proj_w, proj_b);
    k_mlpT<<<144, 256>>>(mlp_w1, mlp_w2);

    k_conv<<<dim3(16, 12, 4), 256>>>(x1, x2);
    k_t1<<<dim3(512, 3, 4), dim3(32, 8)>>>(x1, x2);
    k_attn<<<1024, 256>>>(ln1_g, ln1_b);
    k_mlp<<<1024, 256, 73728>>>(ln2_g, ln2_b, mlp_b1, mlp_b2);
    k_t2<<<dim3(512, 3, 4), dim3(32, 8)>>>();
    k_dct<<<384, 256, 131072>>>();
    k_energy<<<64, 256>>>();
    k_topk<<<4, 256, 65536>>>(fc_w1, fc_b1, fc_w2, fc_b2);
    k_final<<<NTOT / 4 / 256, 256>>>(x1, x2, out);
}

// round 3
// speedup vs baseline: 1.0758x; 1.0515x over previous
#include <cuda_runtime.h>
#include <math.h>

#define Bq   4
#define Cc   96
#define HWp  16384
#define NTOT (Bq*Cc*HWp)          // 6291456

typedef unsigned long long ull;

__device__ __forceinline__ ull pk2(float lo, float hi) {
    ull r; asm("mov.b64 %0,{%1,%2};" : "=l"(r) : "f"(lo), "f"(hi)); return r;
}
__device__ __forceinline__ void upk(ull v, float& lo, float& hi) {
    asm("mov.b64 {%0,%1},%2;" : "=f"(lo), "=f"(hi) : "l"(v));
}
__device__ __forceinline__ void ffma2(ull& d, ull a, ull b) {
    asm("fma.rn.f32x2 %0,%1,%2,%0;" : "+l"(d) : "l"(a), "l"(b));
}
__device__ __forceinline__ float gelu_ex(float x) {
    return 0.5f * x * (1.f + erff(x * 0.70710678118654752f));
}
__device__ __forceinline__ unsigned smem_u32(const void* p) {
    return (unsigned)__cvta_generic_to_shared(p);
}
__device__ __forceinline__ void cp4(unsigned dst, const void* src, int n) {
    asm volatile("cp.async.ca.shared.global [%0],[%1],4,%2;" :: "r"(dst), "l"(src), "r"(n));
}
#define CP_COMMIT() asm volatile("cp.async.commit_group;")
#define CP_WAIT0()  asm volatile("cp.async.wait_group 0;")

// ---------------- device scratch ----------------
__device__ float g_D[128*128];
__device__ float g_DT[128*128];
__device__ float g_Dp[128*128];     // row-paired for stage-1
__device__ float g_weff1[96*96*9];
__device__ float g_weff2[96*96*9];
__device__ float g_WcombT[96*96];
__device__ float g_bcomb[96];
__device__ float g_W1T[96*384];
__device__ float g_W2T[384*96];
__device__ float g_tokA[NTOT];
__device__ float g_tokB[NTOT];
__device__ float g_cross[NTOT];
__device__ float g_dct[NTOT];
__device__ float g_energy[Bq*HWp];
__device__ float g_scale[Bq];

// ---------------- init: DCT-II orthonormal matrix (128) ----------------
__global__ void k_init_dct() {
    int t = blockIdx.x * blockDim.x + threadIdx.x;   // 16384
    int k = t >> 7, i = t & 127;
    float arg = (float)((2 * i + 1) * k) * (1.0f / 256.0f);
    float v = cospif(arg) * 0.125f;
    if (k == 0) v *= 0.70710678118654752440f;
    g_D[k * 128 + i]  = v;
    g_DT[i * 128 + k] = v;
    g_Dp[((k >> 1) * 128 + i) * 2 + (k & 1)] = v;
}

// ---------------- LDC effective weights ----------------
__global__ void k_weff(const float* __restrict__ w, const float* __restrict__ lm,
                       const float* __restrict__ theta, int sel) {
    int t = blockIdx.x * blockDim.x + threadIdx.x;
    if (t >= 96 * 96) return;
    int co = t / 96, ci = t % 96;
    const float* ws = w + t * 9;
    float s = 0.f;
#pragma unroll
    for (int k = 0; k < 9; k++) s += ws[k];
    float scale = 1.f - theta[0] * lm[co * 96 + ci] * s;
    float* out = (sel ? g_weff2 : g_weff1) + t * 9;
#pragma unroll
    for (int k = 0; k < 9; k++) out[k] = ws[k];
    out[4] = ws[4] * scale;
}

// ---------------- fused double conv + residual, cp.async pipelined ----------------
// tokA[token][c] = conv1(x1) + conv2(x2) + 2*(x1+x2)   (token-major output)
__global__ void __launch_bounds__(256, 2)
k_conv(const float* __restrict__ x1, const float* __restrict__ x2) {
    __shared__ __align__(16) float sIn[2][2][34 * 36];
    __shared__ __align__(16) ull  wS[2][2][8][10];
    int tid = threadIdx.x;
    int b   = blockIdx.z;
    int cob = blockIdx.y * 8;
    int bt  = blockIdx.x;
    int y0  = (bt >> 2) * 32, x0 = (bt & 3) * 32;
    const float* Ximg[2] = { x1 + (size_t)b * 96 * HWp, x2 + (size_t)b * 96 * HWp };
    int ty = tid >> 4, tx = tid & 15;
    int py = ty * 2, px = tx * 2;

    // issue async loads for channel ci into buffer buf
    auto issue = [&](int ci, int buf) {
#pragma unroll
        for (int img = 0; img < 2; img++) {
            const float* P = Ximg[img] + (size_t)ci * HWp;
            for (int l = tid; l < 1156; l += 256) {
                int r = l / 34, c = l % 34;
                int gy = y0 - 1 + r, gx = x0 - 1 + c;
                bool ok = (gy >= 0 && gy < 128 && gx >= 0 && gx < 128);
                const float* src = P + (ok ? gy * 128 + gx : 0);
                cp4(smem_u32(&sIn[buf][img][r * 36 + c]), src, ok ? 4 : 0);
            }
        }
        CP_COMMIT();
    };
    auto wload = [&](int ci, int buf) {
        if (tid < 144) {
            int conv = tid / 72, rr = tid % 72, co = rr / 9, k = rr % 9;
            float v = conv ? g_weff2[(cob + co) * 864 + ci * 9 + k]
                           : g_weff1[(cob + co) * 864 + ci * 9 + k];
            wS[buf][conv][co][k] = pk2(v, v);
        }
    };

    issue(0, 0);
    wload(0, 0);

    ull acc[8][2];
#pragma unroll
    for (int i = 0; i < 8; i++) { acc[i][0] = 0ULL; acc[i][1] = 0ULL; }
    const ull TWO = pk2(2.f, 2.f);

    for (int ci = 0; ci < 96; ci++) {
        int cur = ci & 1;
        CP_WAIT0();
        __syncthreads();
        if (ci < 95) { issue(ci + 1, cur ^ 1); wload(ci + 1, cur ^ 1); }

        int cc = ci - cob;   // center-residual channel match
#pragma unroll
        for (int img = 0; img < 2; img++) {
            ull rp[4][3];
#pragma unroll
            for (int r = 0; r < 4; r++) {
                const float* base = &sIn[cur][img][(py + r) * 36 + px];
                float2 a = *(const float2*)base;
                float2 q = *(const float2*)(base + 2);
                rp[r][0] = pk2(a.x, a.y);
                rp[r][1] = pk2(a.y, q.x);
                rp[r][2] = pk2(q.x, q.y);
            }
#pragma unroll
            for (int co = 0; co < 8; co++) {
                const ull* wq = wS[cur][img][co];
                ull r0 = acc[co][0], r1 = acc[co][1];
#pragma unroll
                for (int ky = 0; ky < 3; ky++)
#pragma unroll
                    for (int kx = 0; kx < 3; kx++) {
                        ull w = wq[ky * 3 + kx];
                        ffma2(r0, rp[ky][kx], w);
                        ffma2(r1, rp[ky + 1][kx], w);
                    }
                acc[co][0] = r0; acc[co][1] = r1;
            }
            if (cc >= 0 && cc < 8) {
                ffma2(acc[cc][0], rp[1][1], TWO);
                ffma2(acc[cc][1], rp[2][1], TWO);
            }
        }
    }

    // store token-major: 4 pixels, 8 consecutive channels each
#pragma unroll
    for (int i = 0; i < 2; i++) {
        float lo[8], hi[8];
#pragma unroll
        for (int co = 0; co < 8; co++) upk(acc[co][i], lo[co], hi[co]);
        size_t tokrow = (size_t)b * HWp + (size_t)(y0 + py + i) * 128 + x0 + px;
        float* d0 = g_tokA + tokrow * 96 + cob;
        float* d1 = g_tokA + (tokrow + 1) * 96 + cob;
        ((float4*)d0)[0] = make_float4(lo[0], lo[1], lo[2], lo[3]);
        ((float4*)d0)[1] = make_float4(lo[4], lo[5], lo[6], lo[7]);
        ((float4*)d1)[0] = make_float4(hi[0], hi[1], hi[2], hi[3]);
        ((float4*)d1)[1] = make_float4(hi[4], hi[5], hi[6], hi[7]);
    }
}

// ---------------- prep: Wcomb = proj@Wv, bcomb, MLP transposes ----------------
__global__ void k_prep2(const float* __restrict__ qkv_w, const float* __restrict__ qkv_b,
                        const float* __restrict__ proj_w, const float* __restrict__ proj_b,
                        const float* __restrict__ w1, const float* __restrict__ w2) {
    int blk = blockIdx.x, tid = threadIdx.x;
    if (blk < 96) {
        if (tid < 96) {
            float s = 0.f;
            for (int m = 0; m < 96; m++)
                s += proj_w[blk * 96 + m] * qkv_w[(192 + m) * 96 + tid];
            g_WcombT[tid * 96 + blk] = s;
        }
    } else if (blk == 96) {
        if (tid < 96) {
            float s = proj_b[tid];
            for (int m = 0; m < 96; m++)
                s += proj_w[tid * 96 + m] * qkv_b[192 + m];
            g_bcomb[tid] = s;
        }
    } else {
        int t = (blk - 97) * 256 + tid;
        if (t < 96 * 384) {
            { int k = t / 384, j = t % 384; g_W1T[t] = w1[j * 96 + k]; }
            { int k = t / 96,  i = t % 96;  g_W2T[t] = w2[i * 384 + k]; }
        }
    }
}

// ---------------- swin attention (folded), 8 tokens/warp, f32x2 ----------------
__global__ void __launch_bounds__(256)
k_attn(const float* __restrict__ g1, const float* __restrict__ b1) {
    __shared__ float tns[8][8][96];
    int warp = threadIdx.x >> 5, lane = threadIdx.x & 31;
    int tokbase = blockIdx.x * 64 + warp * 8;
    float tv[8][3];
#pragma unroll
    for (int t = 0; t < 8; t++) {
        const float* tp = g_tokA + (size_t)(tokbase + t) * 96;
        float a = tp[lane], bb = tp[lane + 32], cc = tp[lane + 64];
        tv[t][0] = a; tv[t][1] = bb; tv[t][2] = cc;
        float s = a + bb + cc;
#pragma unroll
        for (int o = 16; o; o >>= 1) s += __shfl_xor_sync(0xffffffff, s, o);
        float m = s * (1.f / 96.f);
        float d0 = a - m, d1 = bb - m, d2 = cc - m;
        float q = d0 * d0 + d1 * d1 + d2 * d2;
#pragma unroll
        for (int o = 16; o; o >>= 1) q += __shfl_xor_sync(0xffffffff, q, o);
        float rstd = rsqrtf(q * (1.f / 96.f) + 1e-5f);
        tns[warp][t][lane]      = d0 * rstd * g1[lane]      + b1[lane];
        tns[warp][t][lane + 32] = d1 * rstd * g1[lane + 32] + b1[lane + 32];
        tns[warp][t][lane + 64] = d2 * rstd * g1[lane + 64] + b1[lane + 64];
    }
    __syncwarp();
    ull acc[4][3];
#pragma unroll
    for (int p = 0; p < 4; p++) { acc[p][0] = 0; acc[p][1] = 0; acc[p][2] = 0; }
    for (int k = 0; k < 96; k++) {
        float w0 = g_WcombT[k * 96 + lane];
        float w1 = g_WcombT[k * 96 + lane + 32];
        float w2 = g_WcombT[k * 96 + lane + 64];
        ull W0 = pk2(w0, w0), W1 = pk2(w1, w1), W2 = pk2(w2, w2);
#pragma unroll
        for (int p = 0; p < 4; p++) {
            ull sp = pk2(tns[warp][2 * p][k], tns[warp][2 * p + 1][k]);
            ffma2(acc[p][0], sp, W0);
            ffma2(acc[p][1], sp, W1);
            ffma2(acc[p][2], sp, W2);
        }
    }
#pragma unroll
    for (int p = 0; p < 4; p++) {
#pragma unroll
        for (int c = 0; c < 3; c++) {
            float o0, o1; upk(acc[p][c], o0, o1);
            int ch = lane + 32 * c;
            g_tokB[(size_t)(tokbase + 2 * p) * 96 + ch]     = tv[2 * p][c]     + o0 + g_bcomb[ch];
            g_tokB[(size_t)(tokbase + 2 * p + 1) * 96 + ch] = tv[2 * p + 1][c] + o1 + g_bcomb[ch];
        }
    }
}

// ---------------- swin MLP, 8 tokens/warp, f32x2, j-halved ----------------
__global__ void __launch_bounds__(256)
k_mlp(const float* __restrict__ g2, const float* __restrict__ b2,
      const float* __restrict__ mb1, const float* __restrict__ mb2) {
    extern __shared__ float sm[];
    float* tn2 = sm;           // [8][8][96]
    float* hs  = sm + 6144;    // [8][8][192]
    int warp = threadIdx.x >> 5, lane = threadIdx.x & 31;
    int tokbase = blockIdx.x * 64 + warp * 8;
    float* tnw = tn2 + warp * 768;
    float* hsw = hs + warp * 1536;
    float tv[8][3];
#pragma unroll
    for (int t = 0; t < 8; t++) {
        const float* tp = g_tokB + (size_t)(tokbase + t) * 96;
        float a = tp[lane], bb = tp[lane + 32], cc = tp[lane + 64];
        tv[t][0] = a; tv[t][1] = bb; tv[t][2] = cc;
        float s = a + bb + cc;
#pragma unroll
        for (int o = 16; o; o >>= 1) s += __shfl_xor_sync(0xffffffff, s, o);
        float m = s * (1.f / 96.f);
        float d0 = a - m, d1 = bb - m, d2 = cc - m;
        float q = d0 * d0 + d1 * d1 + d2 * d2;
#pragma unroll
        for (int o = 16; o; o >>= 1) q += __shfl_xor_sync(0xffffffff, q, o);
        float rstd = rsqrtf(q * (1.f / 96.f) + 1e-5f);
        tnw[t * 96 + lane]      = d0 * rstd * g2[lane]      + b2[lane];
        tnw[t * 96 + lane + 32] = d1 * rstd * g2[lane + 32] + b2[lane + 32];
        tnw[t * 96 + lane + 64] = d2 * rstd * g2[lane + 64] + b2[lane + 64];
    }
    __syncwarp();
    ull oacc[4][3];
#pragma unroll
    for (int p = 0; p < 4; p++) { oacc[p][0] = 0; oacc[p][1] = 0; oacc[p][2] = 0; }

    for (int half = 0; half < 2; half++) {
        ull h[4][6];
#pragma unroll
        for (int p = 0; p < 4; p++)
#pragma unroll
            for (int r = 0; r < 6; r++) h[p][r] = 0;
        const float* w1p = g_W1T + half * 192 + lane;
        for (int k = 0; k < 96; k++) {
            ull W[6];
#pragma unroll
            for (int r = 0; r < 6; r++) {
                float wv = w1p[k * 384 + 32 * r];
                W[r] = pk2(wv, wv);
            }
#pragma unroll
            for (int p = 0; p < 4; p++) {
                ull sp = pk2(tnw[2 * p * 96 + k], tnw[(2 * p + 1) * 96 + k]);
#pragma unroll
                for (int r = 0; r < 6; r++) ffma2(h[p][r], sp, W[r]);
            }
        }
#pragma unroll
        for (int p = 0; p < 4; p++)
#pragma unroll
            for (int r = 0; r < 6; r++) {
                int j = lane + 32 * r;
                float bias = mb1[half * 192 + j];
                float x0, x1; upk(h[p][r], x0, x1);
                hsw[(2 * p) * 192 + j]     = gelu_ex(x0 + bias);
                hsw[(2 * p + 1) * 192 + j] = gelu_ex(x1 + bias);
            }
        __syncwarp();
        const float* w2p = g_W2T + (size_t)(half * 192) * 96;
        for (int j = 0; j < 192; j++) {
            float u0 = w2p[j * 96 + lane];
            float u1 = w2p[j * 96 + lane + 32];
            float u2 = w2p[j * 96 + lane + 64];
            ull U0 = pk2(u0, u0), U1 = pk2(u1, u1), U2 = pk2(u2, u2);
#pragma unroll
            for (int p = 0; p < 4; p++) {
                ull hp = pk2(hsw[2 * p * 192 + j], hsw[(2 * p + 1) * 192 + j]);
                ffma2(oacc[p][0], hp, U0);
                ffma2(oacc[p][1], hp, U1);
                ffma2(oacc[p][2], hp, U2);
            }
        }
        __syncwarp();
    }
#pragma unroll
    for (int p = 0; p < 4; p++) {
#pragma unroll
        for (int c = 0; c < 3; c++) {
            float o0, o1; upk(oacc[p][c], o0, o1);
            int ch = lane + 32 * c;
            g_tokA[(size_t)(tokbase + 2 * p) * 96 + ch]     = tv[2 * p][c]     + o0 + mb2[ch];
            g_tokA[(size_t)(tokbase + 2 * p + 1) * 96 + ch] = tv[2 * p + 1][c] + o1 + mb2[ch];
        }
    }
}

// ---------------- transpose token-major -> CHW ----------------
__global__ void k_t2() {
    __shared__ float tile[32][33];
    int b = blockIdx.z, c0 = blockIdx.y * 32, p0 = blockIdx.x * 32;
    int tx = threadIdx.x, ty0 = threadIdx.y;
    for (int yy = ty0; yy < 32; yy += 8)
        tile[yy][tx] = g_tokA[(size_t)(b * HWp + p0 + yy) * 96 + c0 + tx];
    __syncthreads();
    for (int yy = ty0; yy < 32; yy += 8)
        g_cross[(size_t)(b * 96 + c0 + yy) * HWp + p0 + tx] = tile[tx][yy];
}

// ---------------- 2D DCT per (b,c), f32x2 both stages ----------------
__global__ void __launch_bounds__(256) k_dct() {
    extern __shared__ float sm[];
    float* Xs = sm;
    float* Ys = sm + 16384;
    int bc = blockIdx.x;
    int tid = threadIdx.x;
    const float4* src = (const float4*)(g_cross + (size_t)bc * HWp);
    float4* Xs4 = (float4*)Xs;
    for (int l = tid; l < 4096; l += 256) Xs4[l] = src[l];
    __syncthreads();

    int jq = tid & 31;
    int ig = tid >> 5;
    int j0 = 2 * jq, j2 = 64 + 2 * jq;

    for (int ii = 0; ii < 8; ii++) {
        int ip = ig + ii * 8;
        ull a00 = 0, a01 = 0, a10 = 0, a11 = 0;
        const float2* dp = ((const float2*)g_Dp) + ip * 128;
#pragma unroll 4
        for (int k = 0; k < 128; k++) {
            float2 d = dp[k];
            ull D0 = pk2(d.x, d.x), D1 = pk2(d.y, d.y);
            ull xA = *(const ull*)&Xs[k * 128 + j0];
            ull xB = *(const ull*)&Xs[k * 128 + j2];
            ffma2(a00, xA, D0); ffma2(a01, xB, D0);
            ffma2(a10, xA, D1); ffma2(a11, xB, D1);
        }
        *(ull*)&Ys[(2 * ip) * 128 + j0]     = a00;
        *(ull*)&Ys[(2 * ip) * 128 + j2]     = a01;
        *(ull*)&Ys[(2 * ip + 1) * 128 + j0] = a10;
        *(ull*)&Ys[(2 * ip + 1) * 128 + j2] = a11;
    }
    __syncthreads();

    ull acc[8][4];
#pragma unroll
    for (int ii = 0; ii < 8; ii++)
#pragma unroll
        for (int q = 0; q < 4; q++) acc[ii][q] = 0;
    for (int k = 0; k < 128; k++) {
        ull dtA = *(const ull*)&g_DT[k * 128 + j0];
        ull dtB = *(const ull*)&g_DT[k * 128 + j2];
#pragma unroll
        for (int ii = 0; ii < 8; ii++) {
            int ip = ig + ii * 8;
            float y0 = Ys[(2 * ip) * 128 + k];
            float y1 = Ys[(2 * ip + 1) * 128 + k];
            ull Y0 = pk2(y0, y0), Y1 = pk2(y1, y1);
            ffma2(acc[ii][0], dtA, Y0); ffma2(acc[ii][1], dtB, Y0);
            ffma2(acc[ii][2], dtA, Y1); ffma2(acc[ii][3], dtB, Y1);
        }
    }
    float* dst = g_dct + (size_t)bc * HWp;
#pragma unroll
    for (int ii = 0; ii < 8; ii++) {
        int ip = ig + ii * 8;
        *(ull*)&dst[(2 * ip) * 128 + j0]     = acc[ii][0];
        *(ull*)&dst[(2 * ip) * 128 + j2]     = acc[ii][1];
        *(ull*)&dst[(2 * ip + 1) * 128 + j0] = acc[ii][2];
        *(ull*)&dst[(2 * ip + 1) * 128 + j2] = acc[ii][3];
    }
}

// ---------------- channel-mean |dct| (float4) ----------------
__global__ void k_energy() {
    int g = blockIdx.x * blockDim.x + threadIdx.x;   // 16384
    int b = g >> 12, p4 = g & 4095;
    const float4* base = (const float4*)(g_dct + (size_t)b * 96 * HWp) + p4;
    float4 s = make_float4(0.f, 0.f, 0.f, 0.f);
    for (int c = 0; c < 96; c++) {
        float4 v = base[(size_t)c * 4096];
        s.x += fabsf(v.x); s.y += fabsf(v.y); s.z += fabsf(v.z); s.w += fabsf(v.w);
    }
    float inv = 1.f / 96.f;
    s.x *= inv; s.y *= inv; s.z *= inv; s.w *= inv;
    ((float4*)(g_energy + b * HWp))[p4] = s;
}

// ---------------- top-96 via histogram threshold + rank sort ----------------
__global__ void __launch_bounds__(256)
k_topk(const float* __restrict__ fw1, const float* __restrict__ fb1,
       const float* __restrict__ fw2, const float* __restrict__ fb2) {
    extern __shared__ float e[];                 // 16384 floats
    int* hist = (int*)(e + 16384);               // 4096 ints (reused as cand)
    __shared__ int csum[256];
    __shared__ int s_T, s_cnt;
    __shared__ float tk[96];
    __shared__ float hh[24];
    int b = blockIdx.x, tid = threadIdx.x;

    const float4* src = (const float4*)(g_energy + b * HWp);
    float4* e4 = (float4*)e;
    for (int l = tid; l < 4096; l += 256) e4[l] = src[l];
    for (int l = tid; l < 4096; l += 256) hist[l] = 0;
    __syncthreads();
    // histogram on top 12 bits of positive float (monotonic)
    for (int l = tid; l < 16384; l += 256) {
        int key = (int)(__float_as_uint(e[l]) >> 19);
        atomicAdd(&hist[key], 1);
    }
    __syncthreads();
    // per-thread chunk of 16 bins
    {
        int s = 0;
#pragma unroll
        for (int k = 0; k < 16; k++) s += hist[tid * 16 + k];
        csum[tid] = s;
    }
    __syncthreads();
    if (tid == 0) {
        int run = 0, cstar = 0;
        for (int c = 255; c >= 0; c--) {
            if (run + csum[c] >= 96) { cstar = c; break; }
            run += csum[c];
        }
        int T = cstar * 16;
        for (int k = 15; k >= 0; k--) {
            int bin = cstar * 16 + k;
            if (run + hist[bin] >= 96) { T = bin; break; }
            run += hist[bin];
        }
        s_T = T; s_cnt = 0;
    }
    __syncthreads();
    int T = s_T;
    float* cand = (float*)hist;   // hist no longer needed... but cand IS hist mem; collect after sync
    __syncthreads();
    for (int l = tid; l < 16384; l += 256) {
        float v = e[l];
        if ((int)(__float_as_uint(v) >> 19) >= T) {
            int pos = atomicAdd(&s_cnt, 1);
            if (pos < 4096) cand[pos] = v;
        }
    }
    __syncthreads();
    int M = s_cnt; if (M > 4096) M = 4096;
    for (int i = tid; i < M; i += 256) {
        float v = cand[i];
        int r = 0;
        for (int j = 0; j < M; j++) {
            float u = cand[j];
            r += (u > v) || (u == v && j < i);
        }
        if (r < 96) tk[r] = v;
    }
    __syncthreads();
    if (tid < 24) {
        float s = fb1[tid];
        for (int k = 0; k < 96; k++) s += tk[k] * fw1[tid * 96 + k];
        hh[tid] = fmaxf(s, 0.f);
    }
    __syncthreads();
    if (tid == 0) {
        float a = fb2[0];
        for (int j = 0; j < 24; j++) a += hh[j] * fw2[j];
        g_scale[b] = 1.f + 1.f / (1.f + expf(-a));
    }
}

// ---------------- epilogue (float4) ----------------
__global__ void k_final(const float* __restrict__ x1, const float* __restrict__ x2,
                        float* __restrict__ out) {
    int i = blockIdx.x * blockDim.x + threadIdx.x;   // NTOT/4
    float s = g_scale[i / (96 * HWp / 4)];
    float4 c = ((const float4*)g_cross)[i];
    float4 a = ((const float4*)x1)[i];
    float4 b = ((const float4*)x2)[i];
    float4 o1, o2;
    o1.x = a.x + s * c.x; o1.y = a.y + s * c.y; o1.z = a.z + s * c.z; o1.w = a.w + s * c.w;
    o2.x = b.x + s * c.x; o2.y = b.y + s * c.y; o2.z = b.z + s * c.z; o2.w = b.w + s * c.w;
    ((float4*)out)[i]            = o1;
    ((float4*)out)[NTOT / 4 + i] = o2;
}

extern "C" void kernel_launch(void* const* d_in, const int* in_sizes, int n_in,
                              void* d_out, int out_size) {
    const float* x1     = (const float*)d_in[0];
    const float* x2     = (const float*)d_in[1];
    const float* w_tx1  = (const float*)d_in[2];
    const float* lm1    = (const float*)d_in[3];
    const float* theta1 = (const float*)d_in[4];
    const float* w_tx2  = (const float*)d_in[5];
    const float* lm2    = (const float*)d_in[6];
    const float* theta2 = (const float*)d_in[7];
    const float* ln1_g  = (const float*)d_in[8];
    const float* ln1_b  = (const float*)d_in[9];
    const float* qkv_w  = (const float*)d_in[10];
    const float* qkv_b  = (const float*)d_in[11];
    const float* proj_w = (const float*)d_in[12];
    const float* proj_b = (const float*)d_in[13];
    const float* ln2_g  = (const float*)d_in[14];
    const float* ln2_b  = (const float*)d_in[15];
    const float* mlp_w1 = (const float*)d_in[16];
    const float* mlp_b1 = (const float*)d_in[17];
    const float* mlp_w2 = (const float*)d_in[18];
    const float* mlp_b2 = (const float*)d_in[19];
    const float* fc_w1  = (const float*)d_in[20];
    const float* fc_b1  = (const float*)d_in[21];
    const float* fc_w2  = (const float*)d_in[22];
    const float* fc_b2  = (const float*)d_in[23];
    float* out = (float*)d_out;

    cudaFuncSetAttribute(k_dct,  cudaFuncAttributeMaxDynamicSharedMemorySize, 131072);
    cudaFuncSetAttribute(k_topk, cudaFuncAttributeMaxDynamicSharedMemorySize, 81920);
    cudaFuncSetAttribute(k_mlp,  cudaFuncAttributeMaxDynamicSharedMemorySize, 73728);

    // launch order chosen so k_conv is the 4th launch (ncu capture window)
    k_weff<<<36, 256>>>(w_tx1, lm1, theta1, 0);
    k_weff<<<36, 256>>>(w_tx2, lm2, theta2, 1);
    k_init_dct<<<64, 256>>>();
    k_conv<<<dim3(16, 12, 4), 256>>>(x1, x2);
    k_prep2<<<241, 256>>>(qkv_w, qkv_b, proj_w, proj_b, mlp_w1, mlp_w2);
    k_attn<<<1024, 256>>>(ln1_g, ln1_b);
    k_mlp<<<1024, 256, 73728>>>(ln2_g, ln2_b, mlp_b1, mlp_b2);
    k_t2<<<dim3(512, 3, 4), dim3(32, 8)>>>();
    k_dct<<<384, 256, 131072>>>();
    k_energy<<<64, 256>>>();
    k_topk<<<4, 256, 81920>>>(fc_w1, fc_b1, fc_w2, fc_b2);
    k_final<<<NTOT / 4 / 256, 256>>>(x1, x2, out);
}

// round 4
// speedup vs baseline: 1.1477x; 1.0668x over previous
#include <cuda_runtime.h>
#include <math.h>

#define Bq   4
#define Cc   96
#define HWp  16384
#define NTOT (Bq*Cc*HWp)          // 6291456
#define CROW 40                    // conv smem row stride (floats)

typedef unsigned long long ull;

__device__ __forceinline__ ull pk2(float lo, float hi) {
    ull r; asm("mov.b64 %0,{%1,%2};" : "=l"(r) : "f"(lo), "f"(hi)); return r;
}
__device__ __forceinline__ void upk(ull v, float& lo, float& hi) {
    asm("mov.b64 {%0,%1},%2;" : "=f"(lo), "=f"(hi) : "l"(v));
}
__device__ __forceinline__ void ffma2(ull& d, ull a, ull b) {
    asm("fma.rn.f32x2 %0,%1,%2,%0;" : "+l"(d) : "l"(a), "l"(b));
}
__device__ __forceinline__ float gelu_ex(float x) {
    return 0.5f * x * (1.f + erff(x * 0.70710678118654752f));
}
__device__ __forceinline__ unsigned smem_u32(const void* p) {
    return (unsigned)__cvta_generic_to_shared(p);
}
__device__ __forceinline__ void cp16(unsigned dst, const void* src, int n) {
    asm volatile("cp.async.cg.shared.global [%0],[%1],16,%2;" :: "r"(dst), "l"(src), "r"(n));
}
#define CP_COMMIT() asm volatile("cp.async.commit_group;")
#define CP_WAIT0()  asm volatile("cp.async.wait_group 0;")

// ---------------- device scratch ----------------
__device__ float g_D[128*128];
__device__ float g_DT[128*128];
__device__ float g_Dp[128*128];
__device__ float g_weff1[96*96*9];
__device__ float g_weff2[96*96*9];
__device__ float g_WcombT[96*96];
__device__ float g_bcomb[96];
__device__ float g_W1T[96*384];
__device__ float g_W2T[384*96];
__device__ float g_tokA[NTOT];
__device__ float g_tokB[NTOT];
__device__ float g_cross[NTOT];
__device__ float g_dct[NTOT];
__device__ float g_energy[Bq*HWp];
__device__ float g_scale[Bq];

// ---------------- init: DCT-II orthonormal matrix (128) ----------------
__global__ void k_init_dct() {
    int t = blockIdx.x * blockDim.x + threadIdx.x;   // 16384
    int k = t >> 7, i = t & 127;
    float arg = (float)((2 * i + 1) * k) * (1.0f / 256.0f);
    float v = cospif(arg) * 0.125f;
    if (k == 0) v *= 0.70710678118654752440f;
    g_D[k * 128 + i]  = v;
    g_DT[i * 128 + k] = v;
    g_Dp[((k >> 1) * 128 + i) * 2 + (k & 1)] = v;
}

// ---------------- LDC effective weights (both convs in one launch) ----------------
__global__ void k_weff(const float* __restrict__ w1in, const float* __restrict__ lm1,
                       const float* __restrict__ th1,
                       const float* __restrict__ w2in, const float* __restrict__ lm2,
                       const float* __restrict__ th2) {
    int sel = blockIdx.x >= 36;
    int t = (blockIdx.x - (sel ? 36 : 0)) * 256 + threadIdx.x;
    if (t >= 96 * 96) return;
    const float* w  = sel ? w2in : w1in;
    const float* lm = sel ? lm2 : lm1;
    float theta = sel ? th2[0] : th1[0];
    const float* ws = w + t * 9;
    float s = 0.f;
#pragma unroll
    for (int k = 0; k < 9; k++) s += ws[k];
    float scale = 1.f - theta * lm[t] * s;
    float* out = (sel ? g_weff2 : g_weff1) + t * 9;
#pragma unroll
    for (int k = 0; k < 9; k++) out[k] = ws[k];
    out[4] = ws[4] * scale;
}

// ---------------- fused double conv + residual, hoisted addressing ----------------
// tokA[token][c] = conv1(x1) + conv2(x2) + 2*(x1+x2)   (token-major output)
// smem tile per image: 34 rows x 40 floats; global cols covered [x0-4, x0+36)
__global__ void __launch_bounds__(256, 2)
k_conv(const float* __restrict__ x1, const float* __restrict__ x2) {
    __shared__ __align__(16) float sIn[2][2][34 * CROW];
    __shared__ __align__(16) ull  wS[2][2][8][10];
    int tid = threadIdx.x;
    int b   = blockIdx.z;
    int cob = blockIdx.y * 8;
    int bt  = blockIdx.x;
    int y0  = (bt >> 2) * 32, x0 = (bt & 3) * 32;
    const float* Ximg[2] = { x1 + (size_t)b * 96 * HWp, x2 + (size_t)b * 96 * HWp };
    int ty = tid >> 4, tx = tid & 15;
    int py = ty * 2, px = tx * 2;

    // ---- precompute load slots (channel-invariant) ----
    // 680 chunks: img(2) x row(34) x chunk(10), each 16B
    const char* gsrc[3]; unsigned sdst[3]; int csz[3];
    int nslot = 0;
#pragma unroll
    for (int s = tid; s < 680; s += 256) {
        int img = s / 340, rem = s % 340, r = rem / 10, ch = rem % 10;
        int gy = y0 - 1 + r;
        int gxs = x0 - 4 + ch * 4;
        bool ok = (gy >= 0) && (gy < 128) && (gxs >= 0) && (gxs < 128);
        int goff = ok ? (gy * 128 + gxs) : 0;
        gsrc[nslot] = (const char*)(Ximg[img] + goff);
        sdst[nslot] = smem_u32(&sIn[0][img][r * CROW + ch * 4]);
        csz[nslot]  = ok ? 16 : 0;
        nslot++;
    }

    auto issue = [&](int ci, int buf) {
        unsigned bofs = buf ? (unsigned)(2 * 34 * CROW * 4) : 0u;
        size_t gofs = (size_t)ci * (HWp * 4);
#pragma unroll
        for (int n = 0; n < 3; n++)
            if (n < nslot) cp16(sdst[n] + bofs, gsrc[n] + gofs, csz[n]);
        CP_COMMIT();
    };
    auto wload = [&](int ci, int buf) {
        if (tid < 144) {
            int conv = tid / 72, rr = tid % 72, co = rr / 9, k = rr % 9;
            float v = conv ? g_weff2[(cob + co) * 864 + ci * 9 + k]
                           : g_weff1[(cob + co) * 864 + ci * 9 + k];
            wS[buf][conv][co][k] = pk2(v, v);
        }
    };

    issue(0, 0);
    wload(0, 0);

    ull acc[8][2];
#pragma unroll
    for (int i = 0; i < 8; i++) { acc[i][0] = 0ULL; acc[i][1] = 0ULL; }
    const ull TWO = pk2(2.f, 2.f);

    for (int ci = 0; ci < 96; ci++) {
        int cur = ci & 1;
        CP_WAIT0();
        __syncthreads();
        if (ci < 95) { issue(ci + 1, cur ^ 1); wload(ci + 1, cur ^ 1); }

        int cc = ci - cob;
#pragma unroll
        for (int img = 0; img < 2; img++) {
            ull rp[4][3];
#pragma unroll
            for (int i = 0; i < 4; i++) {
                const float2* base = (const float2*)&sIn[cur][img][(py + i) * CROW + px + 2];
                float2 L0 = base[0], L1 = base[1], L2 = base[2];
                rp[i][0] = pk2(L0.y, L1.x);
                rp[i][1] = pk2(L1.x, L1.y);
                rp[i][2] = pk2(L1.y, L2.x);
            }
#pragma unroll
            for (int co = 0; co < 8; co++) {
                const ull* wq = wS[cur][img][co];
                ull r0 = acc[co][0], r1 = acc[co][1];
#pragma unroll
                for (int ky = 0; ky < 3; ky++)
#pragma unroll
                    for (int kx = 0; kx < 3; kx++) {
                        ull w = wq[ky * 3 + kx];
                        ffma2(r0, rp[ky][kx], w);
                        ffma2(r1, rp[ky + 1][kx], w);
                    }
                acc[co][0] = r0; acc[co][1] = r1;
            }
            if (cc >= 0 && cc < 8) {
                ffma2(acc[cc][0], rp[1][1], TWO);
                ffma2(acc[cc][1], rp[2][1], TWO);
            }
        }
    }

#pragma unroll
    for (int i = 0; i < 2; i++) {
        float lo[8], hi[8];
#pragma unroll
        for (int co = 0; co < 8; co++) upk(acc[co][i], lo[co], hi[co]);
        size_t tokrow = (size_t)b * HWp + (size_t)(y0 + py + i) * 128 + x0 + px;
        float* d0 = g_tokA + tokrow * 96 + cob;
        float* d1 = g_tokA + (tokrow + 1) * 96 + cob;
        ((float4*)d0)[0] = make_float4(lo[0], lo[1], lo[2], lo[3]);
        ((float4*)d0)[1] = make_float4(lo[4], lo[5], lo[6], lo[7]);
        ((float4*)d1)[0] = make_float4(hi[0], hi[1], hi[2], hi[3]);
        ((float4*)d1)[1] = make_float4(hi[4], hi[5], hi[6], hi[7]);
    }
}

// ---------------- prep: Wcomb = proj@Wv, bcomb, MLP transposes ----------------
__global__ void k_prep2(const float* __restrict__ qkv_w, const float* __restrict__ qkv_b,
                        const float* __restrict__ proj_w, const float* __restrict__ proj_b,
                        const float* __restrict__ w1, const float* __restrict__ w2) {
    int blk = blockIdx.x, tid = threadIdx.x;
    if (blk < 96) {
        if (tid < 96) {
            float s = 0.f;
            for (int m = 0; m < 96; m++)
                s += proj_w[blk * 96 + m] * qkv_w[(192 + m) * 96 + tid];
            g_WcombT[tid * 96 + blk] = s;
        }
    } else if (blk == 96) {
        if (tid < 96) {
            float s = proj_b[tid];
            for (int m = 0; m < 96; m++)
                s += proj_w[tid * 96 + m] * qkv_b[192 + m];
            g_bcomb[tid] = s;
        }
    } else {
        int t = (blk - 97) * 256 + tid;
        if (t < 96 * 384) {
            { int k = t / 384, j = t % 384; g_W1T[t] = w1[j * 96 + k]; }
            { int k = t / 96,  i = t % 96;  g_W2T[t] = w2[i * 384 + k]; }
        }
    }
}

// ---------------- swin attention (folded), 8 tokens/warp, f32x2 ----------------
__global__ void __launch_bounds__(256)
k_attn(const float* __restrict__ g1, const float* __restrict__ b1) {
    __shared__ float tns[8][8][96];
    int warp = threadIdx.x >> 5, lane = threadIdx.x & 31;
    int tokbase = blockIdx.x * 64 + warp * 8;
    float tv[8][3];
#pragma unroll
    for (int t = 0; t < 8; t++) {
        const float* tp = g_tokA + (size_t)(tokbase + t) * 96;
        float a = tp[lane], bb = tp[lane + 32], cc = tp[lane + 64];
        tv[t][0] = a; tv[t][1] = bb; tv[t][2] = cc;
        float s = a + bb + cc;
#pragma unroll
        for (int o = 16; o; o >>= 1) s += __shfl_xor_sync(0xffffffff, s, o);
        float m = s * (1.f / 96.f);
        float d0 = a - m, d1 = bb - m, d2 = cc - m;
        float q = d0 * d0 + d1 * d1 + d2 * d2;
#pragma unroll
        for (int o = 16; o; o >>= 1) q += __shfl_xor_sync(0xffffffff, q, o);
        float rstd = rsqrtf(q * (1.f / 96.f) + 1e-5f);
        tns[warp][t][lane]      = d0 * rstd * g1[lane]      + b1[lane];
        tns[warp][t][lane + 32] = d1 * rstd * g1[lane + 32] + b1[lane + 32];
        tns[warp][t][lane + 64] = d2 * rstd * g1[lane + 64] + b1[lane + 64];
    }
    __syncwarp();
    ull acc[4][3];
#pragma unroll
    for (int p = 0; p < 4; p++) { acc[p][0] = 0; acc[p][1] = 0; acc[p][2] = 0; }
    for (int k = 0; k < 96; k++) {
        float w0 = g_WcombT[k * 96 + lane];
        float w1 = g_WcombT[k * 96 + lane + 32];
        float w2 = g_WcombT[k * 96 + lane + 64];
        ull W0 = pk2(w0, w0), W1 = pk2(w1, w1), W2 = pk2(w2, w2);
#pragma unroll
        for (int p = 0; p < 4; p++) {
            ull sp = pk2(tns[warp][2 * p][k], tns[warp][2 * p + 1][k]);
            ffma2(acc[p][0], sp, W0);
            ffma2(acc[p][1], sp, W1);
            ffma2(acc[p][2], sp, W2);
        }
    }
#pragma unroll
    for (int p = 0; p < 4; p++) {
#pragma unroll
        for (int c = 0; c < 3; c++) {
            float o0, o1; upk(acc[p][c], o0, o1);
            int ch = lane + 32 * c;
            g_tokB[(size_t)(tokbase + 2 * p) * 96 + ch]     = tv[2 * p][c]     + o0 + g_bcomb[ch];
            g_tokB[(size_t)(tokbase + 2 * p + 1) * 96 + ch] = tv[2 * p + 1][c] + o1 + g_bcomb[ch];
        }
    }
}

// ---------------- swin MLP, 8 tokens/warp, f32x2, j-halved ----------------
__global__ void __launch_bounds__(256)
k_mlp(const float* __restrict__ g2, const float* __restrict__ b2,
      const float* __restrict__ mb1, const float* __restrict__ mb2) {
    extern __shared__ float sm[];
    float* tn2 = sm;           // [8][8][96]
    float* hs  = sm + 6144;    // [8][8][192]
    int warp = threadIdx.x >> 5, lane = threadIdx.x & 31;
    int tokbase = blockIdx.x * 64 + warp * 8;
    float* tnw = tn2 + warp * 768;
    float* hsw = hs + warp * 1536;
    float tv[8][3];
#pragma unroll
    for (int t = 0; t < 8; t++) {
        const float* tp = g_tokB + (size_t)(tokbase + t) * 96;
        float a = tp[lane], bb = tp[lane + 32], cc = tp[lane + 64];
        tv[t][0] = a; tv[t][1] = bb; tv[t][2] = cc;
        float s = a + bb + cc;
#pragma unroll
        for (int o = 16; o; o >>= 1) s += __shfl_xor_sync(0xffffffff, s, o);
        float m = s * (1.f / 96.f);
        float d0 = a - m, d1 = bb - m, d2 = cc - m;
        float q = d0 * d0 + d1 * d1 + d2 * d2;
#pragma unroll
        for (int o = 16; o; o >>= 1) q += __shfl_xor_sync(0xffffffff, q, o);
        float rstd = rsqrtf(q * (1.f / 96.f) + 1e-5f);
        tnw[t * 96 + lane]      = d0 * rstd * g2[lane]      + b2[lane];
        tnw[t * 96 + lane + 32] = d1 * rstd * g2[lane + 32] + b2[lane + 32];
        tnw[t * 96 + lane + 64] = d2 * rstd * g2[lane + 64] + b2[lane + 64];
    }
    __syncwarp();
    ull oacc[4][3];
#pragma unroll
    for (int p = 0; p < 4; p++) { oacc[p][0] = 0; oacc[p][1] = 0; oacc[p][2] = 0; }

    for (int half = 0; half < 2; half++) {
        ull h[4][6];
#pragma unroll
        for (int p = 0; p < 4; p++)
#pragma unroll
            for (int r = 0; r < 6; r++) h[p][r] = 0;
        const float* w1p = g_W1T + half * 192 + lane;
        for (int k = 0; k < 96; k++) {
            ull W[6];
#pragma unroll
            for (int r = 0; r < 6; r++) {
                float wv = w1p[k * 384 + 32 * r];
                W[r] = pk2(wv, wv);
            }
#pragma unroll
            for (int p = 0; p < 4; p++) {
                ull sp = pk2(tnw[2 * p * 96 + k], tnw[(2 * p + 1) * 96 + k]);
#pragma unroll
                for (int r = 0; r < 6; r++) ffma2(h[p][r], sp, W[r]);
            }
        }
#pragma unroll
        for (int p = 0; p < 4; p++)
#pragma unroll
            for (int r = 0; r < 6; r++) {
                int j = lane + 32 * r;
                float bias = mb1[half * 192 + j];
                float x0, x1; upk(h[p][r], x0, x1);
                hsw[(2 * p) * 192 + j]     = gelu_ex(x0 + bias);
                hsw[(2 * p + 1) * 192 + j] = gelu_ex(x1 + bias);
            }
        __syncwarp();
        const float* w2p = g_W2T + (size_t)(half * 192) * 96;
        for (int j = 0; j < 192; j++) {
            float u0 = w2p[j * 96 + lane];
            float u1 = w2p[j * 96 + lane + 32];
            float u2 = w2p[j * 96 + lane + 64];
            ull U0 = pk2(u0, u0), U1 = pk2(u1, u1), U2 = pk2(u2, u2);
#pragma unroll
            for (int p = 0; p < 4; p++) {
                ull hp = pk2(hsw[2 * p * 192 + j], hsw[(2 * p + 1) * 192 + j]);
                ffma2(oacc[p][0], hp, U0);
                ffma2(oacc[p][1], hp, U1);
                ffma2(oacc[p][2], hp, U2);
            }
        }
        __syncwarp();
    }
#pragma unroll
    for (int p = 0; p < 4; p++) {
#pragma unroll
        for (int c = 0; c < 3; c++) {
            float o0, o1; upk(oacc[p][c], o0, o1);
            int ch = lane + 32 * c;
            g_tokA[(size_t)(tokbase + 2 * p) * 96 + ch]     = tv[2 * p][c]     + o0 + mb2[ch];
            g_tokA[(size_t)(tokbase + 2 * p + 1) * 96 + ch] = tv[2 * p + 1][c] + o1 + mb2[ch];
        }
    }
}

// ---------------- transpose token-major -> CHW ----------------
__global__ void k_t2() {
    __shared__ float tile[32][33];
    int b = blockIdx.z, c0 = blockIdx.y * 32, p0 = blockIdx.x * 32;
    int tx = threadIdx.x, ty0 = threadIdx.y;
    for (int yy = ty0; yy < 32; yy += 8)
        tile[yy][tx] = g_tokA[(size_t)(b * HWp + p0 + yy) * 96 + c0 + tx];
    __syncthreads();
    for (int yy = ty0; yy < 32; yy += 8)
        g_cross[(size_t)(b * 96 + c0 + yy) * HWp + p0 + tx] = tile[tx][yy];
}

// ---------------- 2D DCT per (b,c), f32x2 both stages ----------------
__global__ void __launch_bounds__(256) k_dct() {
    extern __shared__ float sm[];
    float* Xs = sm;
    float* Ys = sm + 16384;
    int bc = blockIdx.x;
    int tid = threadIdx.x;
    const float4* src = (const float4*)(g_cross + (size_t)bc * HWp);
    float4* Xs4 = (float4*)Xs;
    for (int l = tid; l < 4096; l += 256) Xs4[l] = src[l];
    __syncthreads();

    int jq = tid & 31;
    int ig = tid >> 5;
    int j0 = 2 * jq, j2 = 64 + 2 * jq;

    for (int ii = 0; ii < 8; ii++) {
        int ip = ig + ii * 8;
        ull a00 = 0, a01 = 0, a10 = 0, a11 = 0;
        const float2* dp = ((const float2*)g_Dp) + ip * 128;
#pragma unroll 4
        for (int k = 0; k < 128; k++) {
            float2 d = dp[k];
            ull D0 = pk2(d.x, d.x), D1 = pk2(d.y, d.y);
            ull xA = *(const ull*)&Xs[k * 128 + j0];
            ull xB = *(const ull*)&Xs[k * 128 + j2];
            ffma2(a00, xA, D0); ffma2(a01, xB, D0);
            ffma2(a10, xA, D1); ffma2(a11, xB, D1);
        }
        *(ull*)&Ys[(2 * ip) * 128 + j0]     = a00;
        *(ull*)&Ys[(2 * ip) * 128 + j2]     = a01;
        *(ull*)&Ys[(2 * ip + 1) * 128 + j0] = a10;
        *(ull*)&Ys[(2 * ip + 1) * 128 + j2] = a11;
    }
    __syncthreads();

    ull acc[8][4];
#pragma unroll
    for (int ii = 0; ii < 8; ii++)
#pragma unroll
        for (int q = 0; q < 4; q++) acc[ii][q] = 0;
    for (int k = 0; k < 128; k++) {
        ull dtA = *(const ull*)&g_DT[k * 128 + j0];
        ull dtB = *(const ull*)&g_DT[k * 128 + j2];
#pragma unroll
        for (int ii = 0; ii < 8; ii++) {
            int ip = ig + ii * 8;
            float y0 = Ys[(2 * ip) * 128 + k];
            float y1 = Ys[(2 * ip + 1) * 128 + k];
            ull Y0 = pk2(y0, y0), Y1 = pk2(y1, y1);
            ffma2(acc[ii][0], dtA, Y0); ffma2(acc[ii][1], dtB, Y0);
            ffma2(acc[ii][2], dtA, Y1); ffma2(acc[ii][3], dtB, Y1);
        }
    }
    float* dst = g_dct + (size_t)bc * HWp;
#pragma unroll
    for (int ii = 0; ii < 8; ii++) {
        int ip = ig + ii * 8;
        *(ull*)&dst[(2 * ip) * 128 + j0]     = acc[ii][0];
        *(ull*)&dst[(2 * ip) * 128 + j2]     = acc[ii][1];
        *(ull*)&dst[(2 * ip + 1) * 128 + j0] = acc[ii][2];
        *(ull*)&dst[(2 * ip + 1) * 128 + j2] = acc[ii][3];
    }
}

// ---------------- channel-mean |dct| (float4) ----------------
__global__ void k_energy() {
    int g = blockIdx.x * blockDim.x + threadIdx.x;   // 16384
    int b = g >> 12, p4 = g & 4095;
    const float4* base = (const float4*)(g_dct + (size_t)b * 96 * HWp) + p4;
    float4 s = make_float4(0.f, 0.f, 0.f, 0.f);
    for (int c = 0; c < 96; c++) {
        float4 v = base[(size_t)c * 4096];
        s.x += fabsf(v.x); s.y += fabsf(v.y); s.z += fabsf(v.z); s.w += fabsf(v.w);
    }
    float inv = 1.f / 96.f;
    s.x *= inv; s.y *= inv; s.z *= inv; s.w *= inv;
    ((float4*)(g_energy + b * HWp))[p4] = s;
}

// ---------------- top-96 via histogram threshold + rank sort ----------------
__global__ void __launch_bounds__(256)
k_topk(const float* __restrict__ fw1, const float* __restrict__ fb1,
       const float* __restrict__ fw2, const float* __restrict__ fb2) {
    extern __shared__ float e[];                 // 16384 floats
    int* hist = (int*)(e + 16384);               // 4096 ints (reused as cand)
    __shared__ int csum[256];
    __shared__ int s_T, s_cnt;
    __shared__ float tk[96];
    __shared__ float hh[24];
    int b = blockIdx.x, tid = threadIdx.x;

    const float4* src = (const float4*)(g_energy + b * HWp);
    float4* e4 = (float4*)e;
    for (int l = tid; l < 4096; l += 256) e4[l] = src[l];
    for (int l = tid; l < 4096; l += 256) hist[l] = 0;
    __syncthreads();
    for (int l = tid; l < 16384; l += 256) {
        int key = (int)(__float_as_uint(e[l]) >> 19);
        atomicAdd(&hist[key], 1);
    }
    __syncthreads();
    {
        int s = 0;
#pragma unroll
        for (int k = 0; k < 16; k++) s += hist[tid * 16 + k];
        csum[tid] = s;
    }
    __syncthreads();
    if (tid == 0) {
        int run = 0, cstar = 0;
        for (int c = 255; c >= 0; c--) {
            if (run + csum[c] >= 96) { cstar = c; break; }
            run += csum[c];
        }
        int T = cstar * 16;
        for (int k = 15; k >= 0; k--) {
            int bin = cstar * 16 + k;
            if (run + hist[bin] >= 96) { T = bin; break; }
            run += hist[bin];
        }
        s_T = T; s_cnt = 0;
    }
    __syncthreads();
    int T = s_T;
    float* cand = (float*)hist;
    __syncthreads();
    for (int l = tid; l < 16384; l += 256) {
        float v = e[l];
        if ((int)(__float_as_uint(v) >> 19) >= T) {
            int pos = atomicAdd(&s_cnt, 1);
            if (pos < 4096) cand[pos] = v;
        }
    }
    __syncthreads();
    int M = s_cnt; if (M > 4096) M = 4096;
    for (int i = tid; i < M; i += 256) {
        float v = cand[i];
        int r = 0;
        for (int j = 0; j < M; j++) {
            float u = cand[j];
            r += (u > v) || (u == v && j < i);
        }
        if (r < 96) tk[r] = v;
    }
    __syncthreads();
    if (tid < 24) {
        float s = fb1[tid];
        for (int k = 0; k < 96; k++) s += tk[k] * fw1[tid * 96 + k];
        hh[tid] = fmaxf(s, 0.f);
    }
    __syncthreads();
    if (tid == 0) {
        float a = fb2[0];
        for (int j = 0; j < 24; j++) a += hh[j] * fw2[j];
        g_scale[b] = 1.f + 1.f / (1.f + expf(-a));
    }
}

// ---------------- epilogue (float4) ----------------
__global__ void k_final(const float* __restrict__ x1, const float* __restrict__ x2,
                        float* __restrict__ out) {
    int i = blockIdx.x * blockDim.x + threadIdx.x;   // NTOT/4
    float s = g_scale[i / (96 * HWp / 4)];
    float4 c = ((const float4*)g_cross)[i];
    float4 a = ((const float4*)x1)[i];
    float4 b = ((const float4*)x2)[i];
    float4 o1, o2;
    o1.x = a.x + s * c.x; o1.y = a.y + s * c.y; o1.z = a.z + s * c.z; o1.w = a.w + s * c.w;
    o2.x = b.x + s * c.x; o2.y = b.y + s * c.y; o2.z = b.z + s * c.z; o2.w = b.w + s * c.w;
    ((float4*)out)[i]            = o1;
    ((float4*)out)[NTOT / 4 + i] = o2;
}

extern "C" void kernel_launch(void* const* d_in, const int* in_sizes, int n_in,
                              void* d_out, int out_size) {
    const float* x1     = (const float*)d_in[0];
    const float* x2     = (const float*)d_in[1];
    const float* w_tx1  = (const float*)d_in[2];
    const float* lm1    = (const float*)d_in[3];
    const float* theta1 = (const float*)d_in[4];
    const float* w_tx2  = (const float*)d_in[5];
    const float* lm2    = (const float*)d_in[6];
    const float* theta2 = (const float*)d_in[7];
    const float* ln1_g  = (const float*)d_in[8];
    const float* ln1_b  = (const float*)d_in[9];
    const float* qkv_w  = (const float*)d_in[10];
    const float* qkv_b  = (const float*)d_in[11];
    const float* proj_w = (const float*)d_in[12];
    const float* proj_b = (const float*)d_in[13];
    const float* ln2_g  = (const float*)d_in[14];
    const float* ln2_b  = (const float*)d_in[15];
    const float* mlp_w1 = (const float*)d_in[16];
    const float* mlp_b1 = (const float*)d_in[17];
    const float* mlp_w2 = (const float*)d_in[18];
    const float* mlp_b2 = (const float*)d_in[19];
    const float* fc_w1  = (const float*)d_in[20];
    const float* fc_b1  = (const float*)d_in[21];
    const float* fc_w2  = (const float*)d_in[22];
    const float* fc_b2  = (const float*)d_in[23];
    float* out = (float*)d_out;

    cudaFuncSetAttribute(k_dct,  cudaFuncAttributeMaxDynamicSharedMemorySize, 131072);
    cudaFuncSetAttribute(k_topk, cudaFuncAttributeMaxDynamicSharedMemorySize, 81920);
    cudaFuncSetAttribute(k_mlp,  cudaFuncAttributeMaxDynamicSharedMemorySize, 73728);

    // slot 4 (ncu capture) = k_attn
    k_weff<<<72, 256>>>(w_tx1, lm1, theta1, w_tx2, lm2, theta2);
    k_conv<<<dim3(16, 12, 4), 256>>>(x1, x2);
    k_prep2<<<241, 256>>>(qkv_w, qkv_b, proj_w, proj_b, mlp_w1, mlp_w2);
    k_attn<<<1024, 256>>>(ln1_g, ln1_b);
    k_mlp<<<1024, 256, 73728>>>(ln2_g, ln2_b, mlp_b1, mlp_b2);
    k_init_dct<<<64, 256>>>();
    k_t2<<<dim3(512, 3, 4), dim3(32, 8)>>>();
    k_dct<<<384, 256, 131072>>>();
    k_energy<<<64, 256>>>();
    k_topk<<<4, 256, 81920>>>(fc_w1, fc_b1, fc_w2, fc_b2);
    k_final<<<NTOT / 4 / 256, 256>>>(x1, x2, out);
}